// round 9
// baseline (speedup 1.0000x reference)
#include <cuda_runtime.h>
#include <cuda_bf16.h>
#include <math.h>
#include <stdint.h>

// ---------------------------------------------------------------------------
// QuantumTSTransformer: 12-qubit statevector sim, packed f32x2 arithmetic.
//   B=64, T=32, DEGREE=4, sim14 2 layers (96 rots), qff layer (48), DIM=4096.
// circuit_kernel: one CTA per (b,t); 128 threads x 32 packed amps (5 register
// qubits) -> 6 smem phases per layer (12 per circuit) instead of 8 (16).
// Fold swizzle sw5 + per-phase tid-bit deposit keeps all LDS/STS conflict-free.
// Final phase fuses mix[t]*psi and flushes via red.global.add.v2.f32.
// ---------------------------------------------------------------------------

#define NQ       12
#define DIM      4096
#define BATCH    64
#define TSTEPS   32
#define NROTS    96
#define QFFROTS  48
#define DEGREE   4
#define FDIM     64
#define ODIM     8
#define NBLK_CIRC (BATCH * TSTEPS)              // 2048
#define CIRC_SMEM (DIM * 8 + 1024)              // st + coeffs

typedef unsigned long long ull;

// Scratch (device globals: no allocation allowed)
__device__ float2 g_work[DEGREE + 1][BATCH * DIM];   // work_0=base, work_1..4
__device__ float2 g_cs[BATCH * TSTEPS * NROTS];      // (cos(h), sin(h)) per rot
__device__ float2 g_csqff[QFFROTS];

// ---------------- packed f32x2 helpers ----------------
__device__ __forceinline__ ull pk2(float x, float y) {
    ull r; asm("mov.b64 %0, {%1, %2};" : "=l"(r) : "f"(x), "f"(y)); return r;
}
__device__ __forceinline__ ull dup2(float x) { return pk2(x, x); }
__device__ __forceinline__ float2 upk(ull v) {
    float2 r; asm("mov.b64 {%0, %1}, %2;" : "=f"(r.x), "=f"(r.y) : "l"(v)); return r;
}
__device__ __forceinline__ ull swp(ull v) {   // (x,y) -> (y,x)
    ull r;
    asm("{\n\t.reg .b32 lo, hi;\n\tmov.b64 {lo, hi}, %1;\n\tmov.b64 %0, {hi, lo};\n\t}"
        : "=l"(r) : "l"(v));
    return r;
}
__device__ __forceinline__ ull f2mul(ull a, ull b) {
    ull r; asm("mul.rn.f32x2 %0, %1, %2;" : "=l"(r) : "l"(a), "l"(b)); return r;
}
__device__ __forceinline__ ull f2fma(ull a, ull b, ull c) {
    ull r; asm("fma.rn.f32x2 %0, %1, %2, %3;" : "=l"(r) : "l"(a), "l"(b), "l"(c)); return r;
}
__device__ __forceinline__ void red2(float2* p, float2 v) {
    asm volatile("red.global.add.v2.f32 [%0], {%1, %2};"
                 :: "l"(p), "f"(v.x), "f"(v.y) : "memory");
}

// ======================= 4-bit-window machinery (final_kernel) =============
__device__ __forceinline__ uint32_t sw(uint32_t i) { return i ^ ((i >> 4) & 0xFu); }

template<int P0, int P1, int P2, int P3>
__device__ __forceinline__ uint32_t phase_base(int tid) {
    constexpr uint32_t M = (1u << P0) | (1u << P1) | (1u << P2) | (1u << P3);
    uint32_t base = 0;
    int tb = 0;
#pragma unroll
    for (int pos = 0; pos < NQ; ++pos) {
        if (!((M >> pos) & 1u)) {
            base |= ((uint32_t)(tid >> tb) & 1u) << pos;
            ++tb;
        }
    }
    return base;
}
template<int P0, int P1, int P2, int P3>
__device__ __forceinline__ uint32_t pidx(uint32_t base, int j) {
    return base
        | ((j & 1) ? (1u << P0) : 0u)
        | ((j & 2) ? (1u << P1) : 0u)
        | ((j & 4) ? (1u << P2) : 0u)
        | ((j & 8) ? (1u << P3) : 0u);
}

template<int RB>
__device__ __forceinline__ void gry(ull* r, float2 cs) {
    const ull c2 = dup2(cs.x), s2 = dup2(cs.y), ns2 = dup2(-cs.y);
#pragma unroll
    for (int j = 0; j < 16; ++j) {
        if (!(j & (1 << RB))) {
            ull a0 = r[j], a1 = r[j | (1 << RB)];
            r[j]            = f2fma(c2, a0, f2mul(ns2, a1));
            r[j | (1 << RB)] = f2fma(s2, a0, f2mul(c2, a1));
        }
    }
}
template<int RBC, int RBT>
__device__ __forceinline__ void gcrx(ull* r, float2 cs) {
    const ull c2 = dup2(cs.x);
    const ull spm = pk2(cs.y, -cs.y);
#pragma unroll
    for (int j = 0; j < 16; ++j) {
        if ((j & (1 << RBC)) && !(j & (1 << RBT))) {
            ull a0 = r[j], a1 = r[j | (1 << RBT)];
            r[j]             = f2fma(c2, a0, f2mul(spm, swp(a1)));
            r[j | (1 << RBT)] = f2fma(c2, a1, f2mul(spm, swp(a0)));
        }
    }
}

#define PHASE_LOAD(P0,P1,P2,P3)                                            \
    uint32_t base = phase_base<P0,P1,P2,P3>(tid);                          \
    ull r[16];                                                             \
    _Pragma("unroll")                                                      \
    for (int j = 0; j < 16; ++j) r[j] = st[sw(pidx<P0,P1,P2,P3>(base, j))];

#define PHASE_STORE(P0,P1,P2,P3)                                           \
    _Pragma("unroll")                                                      \
    for (int j = 0; j < 16; ++j) st[sw(pidx<P0,P1,P2,P3>(base, j))] = r[j];

__device__ __forceinline__ void phA1(ull* st, const float2* c, int tid) {
    PHASE_LOAD(11, 0, 1, 2);
    gry<0>(r, c[0]);  gry<1>(r, c[11]); gry<2>(r, c[10]); gry<3>(r, c[9]);
    gcrx<1, 0>(r, c[12]); gcrx<2, 1>(r, c[13]); gcrx<3, 2>(r, c[14]);
    PHASE_STORE(11, 0, 1, 2);
}
__device__ __forceinline__ void phA2(ull* st, const float2* c, int tid) {
    PHASE_LOAD(2, 3, 4, 5);
    gry<1>(r, c[8]); gry<2>(r, c[7]); gry<3>(r, c[6]);
    gcrx<1, 0>(r, c[15]); gcrx<2, 1>(r, c[16]); gcrx<3, 2>(r, c[17]);
    PHASE_STORE(2, 3, 4, 5);
}
__device__ __forceinline__ void phA3(ull* st, const float2* c, int tid) {
    PHASE_LOAD(5, 6, 7, 8);
    gry<1>(r, c[5]); gry<2>(r, c[4]); gry<3>(r, c[3]);
    gcrx<1, 0>(r, c[18]); gcrx<2, 1>(r, c[19]); gcrx<3, 2>(r, c[20]);
    PHASE_STORE(5, 6, 7, 8);
}
__device__ __forceinline__ void phA4(ull* st, const float2* c, int tid) {
    PHASE_LOAD(8, 9, 10, 11);
    gry<1>(r, c[2]); gry<2>(r, c[1]);
    gcrx<1, 0>(r, c[21]); gcrx<2, 1>(r, c[22]); gcrx<3, 2>(r, c[23]);
    PHASE_STORE(8, 9, 10, 11);
}
__device__ __forceinline__ void phB1(ull* st, const float2* c, int tid) {
    PHASE_LOAD(1, 0, 11, 10);
    gry<0>(r, c[34]); gry<1>(r, c[35]); gry<2>(r, c[24]); gry<3>(r, c[25]);
    gcrx<1, 0>(r, c[36]); gcrx<2, 1>(r, c[37]); gcrx<3, 2>(r, c[38]);
    PHASE_STORE(1, 0, 11, 10);
}
__device__ __forceinline__ void phB2(ull* st, const float2* c, int tid) {
    PHASE_LOAD(10, 9, 8, 7);
    gry<1>(r, c[26]); gry<2>(r, c[27]); gry<3>(r, c[28]);
    gcrx<1, 0>(r, c[39]); gcrx<2, 1>(r, c[40]); gcrx<3, 2>(r, c[41]);
    PHASE_STORE(10, 9, 8, 7);
}
__device__ __forceinline__ void phB3(ull* st, const float2* c, int tid) {
    PHASE_LOAD(7, 6, 5, 4);
    gry<1>(r, c[29]); gry<2>(r, c[30]); gry<3>(r, c[31]);
    gcrx<1, 0>(r, c[42]); gcrx<2, 1>(r, c[43]); gcrx<3, 2>(r, c[44]);
    PHASE_STORE(7, 6, 5, 4);
}
__device__ __forceinline__ void phB4(ull* st, const float2* c, int tid) {
    PHASE_LOAD(4, 3, 2, 1);
    gry<1>(r, c[32]); gry<2>(r, c[33]);
    gcrx<1, 0>(r, c[45]); gcrx<2, 1>(r, c[46]); gcrx<3, 2>(r, c[47]);
    PHASE_STORE(4, 3, 2, 1);
}
__device__ __forceinline__ void run_layer(ull* st, const float2* c, int tid) {
    phA1(st, c, tid); __syncthreads();
    phA2(st, c, tid); __syncthreads();
    phA3(st, c, tid); __syncthreads();
    phA4(st, c, tid); __syncthreads();
    phB1(st, c, tid); __syncthreads();
    phB2(st, c, tid); __syncthreads();
    phB3(st, c, tid); __syncthreads();
    phB4(st, c, tid); __syncthreads();
}

// ======================= 5-bit-window machinery (circuit_kernel) ===========
// Fold swizzle: bank16 bits = i[0:4] ^ i[4:8] ^ i[8:12]  (XOR-linear)
__device__ __forceinline__ uint32_t sw5(uint32_t i) {
    return i ^ ((i >> 4) & 0xFu) ^ ((i >> 8) & 0xFu);
}

// Window bits P0..P4 get amp bits j0..j4; tid bits 0..6 deposited at D0..D6.
// Deposits chosen so lane bits 0..3 sit at positions with distinct residues
// mod 4 (conflict-free half-warp LDS.64/STS.64 under sw5).
template<int P0,int P1,int P2,int P3,int P4,
         int D0,int D1,int D2,int D3,int D4,int D5,int D6>
struct Ph {
    static __device__ __forceinline__ uint32_t base(int tid) {
        return ((tid & 1)  ? (1u << D0) : 0u)
             | ((tid & 2)  ? (1u << D1) : 0u)
             | ((tid & 4)  ? (1u << D2) : 0u)
             | ((tid & 8)  ? (1u << D3) : 0u)
             | ((tid & 16) ? (1u << D4) : 0u)
             | ((tid & 32) ? (1u << D5) : 0u)
             | ((tid & 64) ? (1u << D6) : 0u);
    }
    static __device__ __forceinline__ uint32_t idx(uint32_t b, int j) {
        return b | ((j & 1)  ? (1u << P0) : 0u)
                 | ((j & 2)  ? (1u << P1) : 0u)
                 | ((j & 4)  ? (1u << P2) : 0u)
                 | ((j & 8)  ? (1u << P3) : 0u)
                 | ((j & 16) ? (1u << P4) : 0u);
    }
};

// Windows (bit space; wire w <-> bit 11-w):
//   chainA: W1={11,0,1,2,3} W2={3,4,5,6,7} W3={7,8,9,10,11}
//   chainB: V1={1,0,11,10,9} V2={9,8,7,6,5} V3={5,4,3,2,1}
typedef Ph<11,0,1,2,3,  4,5,6,7,8,9,10>  PW1;
typedef Ph<3,4,5,6,7,   0,1,2,11,8,9,10> PW2;
typedef Ph<7,8,9,10,11, 0,1,2,3,4,5,6>   PW3;
typedef Ph<1,0,11,10,9, 4,5,2,3,6,7,8>   PV1;
typedef Ph<9,8,7,6,5,   0,1,2,3,4,10,11> PV2;
typedef Ph<5,4,3,2,1,   0,9,6,7,8,10,11> PV3;

template<int RB>
__device__ __forceinline__ void gry5(ull* r, float2 cs) {
    const ull c2 = dup2(cs.x), s2 = dup2(cs.y), ns2 = dup2(-cs.y);
#pragma unroll
    for (int j = 0; j < 32; ++j) {
        if (!(j & (1 << RB))) {
            ull a0 = r[j], a1 = r[j | (1 << RB)];
            r[j]            = f2fma(c2, a0, f2mul(ns2, a1));
            r[j | (1 << RB)] = f2fma(s2, a0, f2mul(c2, a1));
        }
    }
}
template<int RBC, int RBT>
__device__ __forceinline__ void gcrx5(ull* r, float2 cs) {
    const ull c2 = dup2(cs.x);
    const ull spm = pk2(cs.y, -cs.y);
#pragma unroll
    for (int j = 0; j < 32; ++j) {
        if ((j & (1 << RBC)) && !(j & (1 << RBT))) {
            ull a0 = r[j], a1 = r[j | (1 << RBT)];
            r[j]             = f2fma(c2, a0, f2mul(spm, swp(a1)));
            r[j | (1 << RBT)] = f2fma(c2, a1, f2mul(spm, swp(a0)));
        }
    }
}

#define PH5_LOAD(PHT)                                                      \
    uint32_t base = PHT::base(tid);                                        \
    ull r[32];                                                             \
    _Pragma("unroll")                                                      \
    for (int j = 0; j < 32; ++j) r[j] = st[sw5(PHT::idx(base, j))];

#define PH5_STORE(PHT)                                                     \
    _Pragma("unroll")                                                      \
    for (int j = 0; j < 32; ++j) st[sw5(PHT::idx(base, j))] = r[j];

// --- 6 phases of one sim14 layer; RY ring fused into the chain windows ---
// ring1 param for bit b: c[11-b]; ring2: c[24+(11-b)].
// chainA gate ctrl bit m: c[12+m]. chainB ctrl m: m==0 ? c[36] : c[36+12-m].
__device__ __forceinline__ void qA1(ull* st, const float2* c, int tid) {
    PH5_LOAD(PW1);
    gry5<0>(r, c[0]); gry5<1>(r, c[11]); gry5<2>(r, c[10]); gry5<3>(r, c[9]); gry5<4>(r, c[8]);
    gcrx5<1,0>(r, c[12]); gcrx5<2,1>(r, c[13]); gcrx5<3,2>(r, c[14]); gcrx5<4,3>(r, c[15]);
    PH5_STORE(PW1);
}
__device__ __forceinline__ void qA2(ull* st, const float2* c, int tid) {
    PH5_LOAD(PW2);
    gry5<1>(r, c[7]); gry5<2>(r, c[6]); gry5<3>(r, c[5]); gry5<4>(r, c[4]);
    gcrx5<1,0>(r, c[16]); gcrx5<2,1>(r, c[17]); gcrx5<3,2>(r, c[18]); gcrx5<4,3>(r, c[19]);
    PH5_STORE(PW2);
}
__device__ __forceinline__ void qA3(ull* st, const float2* c, int tid) {
    PH5_LOAD(PW3);
    gry5<1>(r, c[3]); gry5<2>(r, c[2]); gry5<3>(r, c[1]);
    gcrx5<1,0>(r, c[20]); gcrx5<2,1>(r, c[21]); gcrx5<3,2>(r, c[22]); gcrx5<4,3>(r, c[23]);
    PH5_STORE(PW3);
}
__device__ __forceinline__ void qB1(ull* st, const float2* c, int tid) {
    PH5_LOAD(PV1);
    gry5<0>(r, c[34]); gry5<1>(r, c[35]); gry5<2>(r, c[24]); gry5<3>(r, c[25]); gry5<4>(r, c[26]);
    gcrx5<1,0>(r, c[36]); gcrx5<2,1>(r, c[37]); gcrx5<3,2>(r, c[38]); gcrx5<4,3>(r, c[39]);
    PH5_STORE(PV1);
}
__device__ __forceinline__ void qB2(ull* st, const float2* c, int tid) {
    PH5_LOAD(PV2);
    gry5<1>(r, c[27]); gry5<2>(r, c[28]); gry5<3>(r, c[29]); gry5<4>(r, c[30]);
    gcrx5<1,0>(r, c[40]); gcrx5<2,1>(r, c[41]); gcrx5<3,2>(r, c[42]); gcrx5<4,3>(r, c[43]);
    PH5_STORE(PV2);
}
__device__ __forceinline__ void qB3(ull* st, const float2* c, int tid) {
    PH5_LOAD(PV3);
    gry5<1>(r, c[31]); gry5<2>(r, c[32]); gry5<3>(r, c[33]);
    gcrx5<1,0>(r, c[44]); gcrx5<2,1>(r, c[45]); gcrx5<3,2>(r, c[46]); gcrx5<4,3>(r, c[47]);
    PH5_STORE(PV3);
}

// ---------------------------------------------------------------------------
// Kernel 1 (merged prep): blocks [0, 5120): zero/init g_work.
//                         blocks [5120, 7168): param projection for bt.
// ---------------------------------------------------------------------------
#define INIT_BLKS ((DEGREE + 1) * BATCH * DIM / 256)   // 5120
__global__ void prep_kernel(const float* __restrict__ x,
                            const float* __restrict__ Wp,
                            const float* __restrict__ bp,
                            const float* __restrict__ qff) {
    if (blockIdx.x < INIT_BLKS) {
        uint32_t e = blockIdx.x * 256 + threadIdx.x;
        float2* flat = &g_work[0][0];
        uint32_t buf = e >> 18;
        uint32_t rem = e & 0x3FFFFu;
        float2 v = make_float2(0.f, 0.f);
        if (buf == 0 && (rem & (DIM - 1)) == 0) v.x = 1.f;
        flat[e] = v;
        return;
    }
    __shared__ float xr[FDIM];
    int bt = blockIdx.x - INIT_BLKS;   // 0..2047
    int r = threadIdx.x;               // 0..255 (only 0..95 produce)
    if (r < FDIM) xr[r] = x[bt * FDIM + r];
    __syncthreads();
    if (r < NROTS) {
        float acc = bp[r];
#pragma unroll
        for (int f = 0; f < FDIM; ++f) acc += xr[f] * Wp[r * FDIM + f];
        float sg = 1.0f / (1.0f + expf(-acc));
        float h = 3.14159265358979323846f * sg;   // theta/2 = pi * sigmoid
        float sv, cv; sincosf(h, &sv, &cv);
        g_cs[bt * NROTS + r] = make_float2(cv, sv);
        if (bt == 0 && r < QFFROTS) {
            float hq = 0.5f * qff[r];
            float sq, cq; sincosf(hq, &sq, &cq);
            g_csqff[r] = make_float2(cq, sq);
        }
    }
}

// ---------------------------------------------------------------------------
// Kernel 2: one polynomial degree. grid = 2048 (one CTA per (b,t)), 128 thr.
// 12 phases per circuit (2 layers x 6); final phase fused with mix+flush.
// ---------------------------------------------------------------------------
__global__ void __launch_bounds__(128, 5)
circuit_kernel(const ull* __restrict__ win, float2* __restrict__ wout,
               const float* __restrict__ mix_re, const float* __restrict__ mix_im) {
    extern __shared__ ull dsm[];
    ull* st = dsm;                            // DIM
    float2* cc = (float2*)(dsm + DIM);        // 96 coeffs + mix at [96]

    const int tid = threadIdx.x;
    const int b = blockIdx.x >> 5;
    const int t = blockIdx.x & 31;

    // load input state (64-bit, coalesced; sw5 alters only bits 0..3)
#pragma unroll
    for (int k = 0; k < 32; ++k) {
        int i = tid + 128 * k;
        st[sw5((uint32_t)i)] = win[b * DIM + i];
    }
    if (tid < NROTS) cc[tid] = g_cs[(b * TSTEPS + t) * NROTS + tid];
    if (tid == NROTS) cc[NROTS] = make_float2(mix_re[t], mix_im[t]);
    __syncthreads();

    // layer 0
    qA1(st, cc, tid); __syncthreads();
    qA2(st, cc, tid); __syncthreads();
    qA3(st, cc, tid); __syncthreads();
    qB1(st, cc, tid); __syncthreads();
    qB2(st, cc, tid); __syncthreads();
    qB3(st, cc, tid); __syncthreads();
    // layer 1 (first 5 phases; last one fused with mix+flush)
    const float2* c1 = cc + 48;
    qA1(st, c1, tid); __syncthreads();
    qA2(st, c1, tid); __syncthreads();
    qA3(st, c1, tid); __syncthreads();
    qB1(st, c1, tid); __syncthreads();
    qB2(st, c1, tid); __syncthreads();
    {   // qB3 without store: mix[t] * psi -> red.global directly
        PH5_LOAD(PV3);
        gry5<1>(r, c1[31]); gry5<2>(r, c1[32]); gry5<3>(r, c1[33]);
        gcrx5<1,0>(r, c1[44]); gcrx5<2,1>(r, c1[45]);
        gcrx5<3,2>(r, c1[46]); gcrx5<4,3>(r, c1[47]);
        float2 mx = cc[NROTS];
        const ull mr2 = dup2(mx.x);
        const ull mpm = pk2(-mx.y, mx.y);   // mul(mpm, swap(v)) = (-mi*vy, mi*vx)
#pragma unroll
        for (int j = 0; j < 32; ++j) {
            uint32_t i = PV3::idx(base, j);
            ull v = f2fma(mr2, r[j], f2mul(mpm, swp(r[j])));
            red2(&wout[b * DIM + i], upk(v));
        }
    }
}

// ---------------------------------------------------------------------------
// Kernel 3: assemble acc, normalize, qff layer, Pauli expvals, output linear.
// grid = 64 (one CTA per batch), 256 threads (4-bit-window machinery).
// ---------------------------------------------------------------------------
__global__ void final_kernel(const float* __restrict__ poly,
                             const float* __restrict__ W_out,
                             const float* __restrict__ b_out,
                             float* __restrict__ out) {
    __shared__ ull st[DIM];
    __shared__ float red[37];            // [0..35] expvals, [36] sumsq
    const int tid = threadIdx.x;
    const int b = blockIdx.x;

    float p[DEGREE + 1];
#pragma unroll
    for (int d = 0; d <= DEGREE; ++d) p[d] = poly[d];
    float sabs = 0.f;
#pragma unroll
    for (int d = 0; d <= DEGREE; ++d) sabs += fabsf(p[d]);
    const float inv_s = 1.f / sabs;

    if (tid == 0) red[36] = 0.f;
    const ull* wflat = (const ull*)&g_work[0][0];
    float lsq = 0.f;
#pragma unroll
    for (int k = 0; k < 16; ++k) {
        int i = tid + 256 * k;
        ull v = 0ull;
#pragma unroll
        for (int d = 0; d <= DEGREE; ++d) {
            ull w = wflat[(size_t)d * (BATCH * DIM) + b * DIM + i];
            v = f2fma(dup2(p[d]), w, v);
        }
        v = f2mul(dup2(inv_s), v);
        st[sw((uint32_t)i)] = v;
        float2 vf = upk(v);
        lsq += vf.x * vf.x + vf.y * vf.y;
    }
#pragma unroll
    for (int o = 16; o > 0; o >>= 1) lsq += __shfl_xor_sync(0xffffffffu, lsq, o);
    if ((tid & 31) == 0) atomicAdd(&red[36], lsq);
    __syncthreads();

    const float f = 1.f / (sqrtf(red[36]) + 1e-9f);
    const ull f2 = dup2(f);
#pragma unroll
    for (int k = 0; k < 16; ++k) {
        int i = tid + 256 * k;
        uint32_t s_ = sw((uint32_t)i);
        st[s_] = f2mul(f2, st[s_]);
    }
    __syncthreads();

    run_layer(st, g_csqff, tid);     // qff: one sim14 layer

    if (tid < 36) red[tid] = 0.f;
    __syncthreads();

    float xx[NQ], yy[NQ], zz[NQ];
#pragma unroll
    for (int w = 0; w < NQ; ++w) { xx[w] = 0.f; yy[w] = 0.f; zz[w] = 0.f; }

#pragma unroll
    for (int k = 0; k < 16; ++k) {
        int i = tid + 256 * k;
        float2 a = upk(st[sw((uint32_t)i)]);
        float n2 = a.x * a.x + a.y * a.y;
#pragma unroll
        for (int w = 0; w < NQ; ++w) {
            int pbit = 11 - w;
            if (((i >> pbit) & 1) == 0) {
                float2 a1 = upk(st[sw((uint32_t)(i | (1 << pbit)))]);
                xx[w] += 2.f * (a.x * a1.x + a.y * a1.y);
                yy[w] += 2.f * (a.x * a1.y - a.y * a1.x);
                zz[w] += n2;
            } else {
                zz[w] -= n2;
            }
        }
    }
#pragma unroll
    for (int w = 0; w < NQ; ++w) {
        atomicAdd(&red[w], xx[w]);
        atomicAdd(&red[12 + w], yy[w]);
        atomicAdd(&red[24 + w], zz[w]);
    }
    __syncthreads();

    if (tid < ODIM) {
        float acc = b_out[tid];
#pragma unroll
        for (int j = 0; j < 36; ++j) acc += W_out[tid * 36 + j] * red[j];
        out[b * ODIM + tid] = acc;
    }
}

// ---------------------------------------------------------------------------
// Inputs (metadata order): x, W_proj, b_proj, poly_coeffs, mix_re, mix_im,
//                          qff_params, W_out, b_out.  Output: float32 [64,8].
// ---------------------------------------------------------------------------
extern "C" void kernel_launch(void* const* d_in, const int* in_sizes, int n_in,
                              void* d_out, int out_size) {
    (void)in_sizes; (void)n_in; (void)out_size;
    const float* x      = (const float*)d_in[0];
    const float* W_proj = (const float*)d_in[1];
    const float* b_proj = (const float*)d_in[2];
    const float* poly   = (const float*)d_in[3];
    const float* mix_re = (const float*)d_in[4];
    const float* mix_im = (const float*)d_in[5];
    const float* qff    = (const float*)d_in[6];
    const float* W_out  = (const float*)d_in[7];
    const float* b_out  = (const float*)d_in[8];
    float* out = (float*)d_out;

    cudaFuncSetAttribute(circuit_kernel,
                         cudaFuncAttributeMaxDynamicSharedMemorySize, CIRC_SMEM);

    prep_kernel<<<INIT_BLKS + BATCH * TSTEPS, 256>>>(x, W_proj, b_proj, qff);

    float2* w0;
    cudaGetSymbolAddress((void**)&w0, g_work);   // base of g_work
    float2* w1 = w0 + 1 * BATCH * DIM;
    float2* w2 = w0 + 2 * BATCH * DIM;
    float2* w3 = w0 + 3 * BATCH * DIM;
    float2* w4 = w0 + 4 * BATCH * DIM;

    circuit_kernel<<<NBLK_CIRC, 128, CIRC_SMEM>>>((const ull*)w0, w1, mix_re, mix_im);
    circuit_kernel<<<NBLK_CIRC, 128, CIRC_SMEM>>>((const ull*)w1, w2, mix_re, mix_im);
    circuit_kernel<<<NBLK_CIRC, 128, CIRC_SMEM>>>((const ull*)w2, w3, mix_re, mix_im);
    circuit_kernel<<<NBLK_CIRC, 128, CIRC_SMEM>>>((const ull*)w3, w4, mix_re, mix_im);

    final_kernel<<<BATCH, 256>>>(poly, W_out, b_out, out);
}

// round 10
// speedup vs baseline: 1.0274x; 1.0274x over previous
#include <cuda_runtime.h>
#include <cuda_bf16.h>
#include <math.h>
#include <stdint.h>

// ---------------------------------------------------------------------------
// QuantumTSTransformer: 12-qubit statevector sim, packed f32x2 arithmetic.
//   B=64, T=32, DEGREE=4, sim14 2 layers (96 rots), qff layer (48), DIM=4096.
// circuit_kernel (R7 core): one CTA per (b,t); state in dynamic smem (32KB) as
// packed (re,im) b64; gates in 8 phases/layer, 4 register-resident qubits
// (16 packed amps/thread, 256 threads, 64 regs, 4 CTAs/SM). First phase loads
// the input state DIRECTLY from global (no staging round trip); final phase
// fuses mix[t]*psi and flushes via red.global.add.v2.f32.
// ---------------------------------------------------------------------------

#define NQ       12
#define DIM      4096
#define BATCH    64
#define TSTEPS   32
#define NROTS    96
#define QFFROTS  48
#define DEGREE   4
#define FDIM     64
#define ODIM     8
#define NBLK_CIRC (BATCH * TSTEPS)              // 2048
#define CIRC_SMEM (DIM * 8 + 1024)              // st + coeffs

typedef unsigned long long ull;

// Scratch (device globals: no allocation allowed)
__device__ float2 g_work[DEGREE + 1][BATCH * DIM];   // work_0=base, work_1..4
__device__ float2 g_cs[BATCH * TSTEPS * NROTS];      // (cos(h), sin(h)) per rot
__device__ float2 g_csqff[QFFROTS];

// ---------------- packed f32x2 helpers ----------------
__device__ __forceinline__ ull pk2(float x, float y) {
    ull r; asm("mov.b64 %0, {%1, %2};" : "=l"(r) : "f"(x), "f"(y)); return r;
}
__device__ __forceinline__ ull dup2(float x) { return pk2(x, x); }
__device__ __forceinline__ float2 upk(ull v) {
    float2 r; asm("mov.b64 {%0, %1}, %2;" : "=f"(r.x), "=f"(r.y) : "l"(v)); return r;
}
__device__ __forceinline__ ull swp(ull v) {   // (x,y) -> (y,x)
    ull r;
    asm("{\n\t.reg .b32 lo, hi;\n\tmov.b64 {lo, hi}, %1;\n\tmov.b64 %0, {hi, lo};\n\t}"
        : "=l"(r) : "l"(v));
    return r;
}
__device__ __forceinline__ ull f2mul(ull a, ull b) {
    ull r; asm("mul.rn.f32x2 %0, %1, %2;" : "=l"(r) : "l"(a), "l"(b)); return r;
}
__device__ __forceinline__ ull f2fma(ull a, ull b, ull c) {
    ull r; asm("fma.rn.f32x2 %0, %1, %2, %3;" : "=l"(r) : "l"(a), "l"(b), "l"(c)); return r;
}
__device__ __forceinline__ void red2(float2* p, float2 v) {
    asm volatile("red.global.add.v2.f32 [%0], {%1, %2};"
                 :: "l"(p), "f"(v.x), "f"(v.y) : "memory");
}

// smem slot swizzle: bijective, conflict-free for all phase patterns
__device__ __forceinline__ uint32_t sw(uint32_t i) { return i ^ ((i >> 4) & 0xFu); }

// base address: deposit 8 tid bits into the amplitude-index bits NOT in {P0..P3}
template<int P0, int P1, int P2, int P3>
__device__ __forceinline__ uint32_t phase_base(int tid) {
    constexpr uint32_t M = (1u << P0) | (1u << P1) | (1u << P2) | (1u << P3);
    uint32_t base = 0;
    int tb = 0;
#pragma unroll
    for (int pos = 0; pos < NQ; ++pos) {
        if (!((M >> pos) & 1u)) {
            base |= ((uint32_t)(tid >> tb) & 1u) << pos;
            ++tb;
        }
    }
    return base;
}

template<int P0, int P1, int P2, int P3>
__device__ __forceinline__ uint32_t pidx(uint32_t base, int j) {
    return base
        | ((j & 1) ? (1u << P0) : 0u)
        | ((j & 2) ? (1u << P1) : 0u)
        | ((j & 4) ? (1u << P2) : 0u)
        | ((j & 8) ? (1u << P3) : 0u);
}

// RY on register-bit RB:  a0' = c a0 - s a1 ; a1' = s a0 + c a1  (componentwise)
template<int RB>
__device__ __forceinline__ void gry(ull* r, float2 cs) {
    const ull c2 = dup2(cs.x), s2 = dup2(cs.y), ns2 = dup2(-cs.y);
#pragma unroll
    for (int j = 0; j < 16; ++j) {
        if (!(j & (1 << RB))) {
            ull a0 = r[j], a1 = r[j | (1 << RB)];
            r[j]            = f2fma(c2, a0, f2mul(ns2, a1));
            r[j | (1 << RB)] = f2fma(s2, a0, f2mul(c2, a1));
        }
    }
}

// CRX: control RBC==1, target RBT.  a0' = c a0 - i s a1 ; a1' = c a1 - i s a0.
//  -i s v = (s*v.y, -s*v.x) = mul((s,-s), swap(v))
template<int RBC, int RBT>
__device__ __forceinline__ void gcrx(ull* r, float2 cs) {
    const ull c2 = dup2(cs.x);
    const ull spm = pk2(cs.y, -cs.y);
#pragma unroll
    for (int j = 0; j < 16; ++j) {
        if ((j & (1 << RBC)) && !(j & (1 << RBT))) {
            ull a0 = r[j], a1 = r[j | (1 << RBT)];
            r[j]             = f2fma(c2, a0, f2mul(spm, swp(a1)));
            r[j | (1 << RBT)] = f2fma(c2, a1, f2mul(spm, swp(a0)));
        }
    }
}

#define PHASE_LOAD(P0,P1,P2,P3)                                            \
    uint32_t base = phase_base<P0,P1,P2,P3>(tid);                          \
    ull r[16];                                                             \
    _Pragma("unroll")                                                      \
    for (int j = 0; j < 16; ++j) r[j] = st[sw(pidx<P0,P1,P2,P3>(base, j))];

#define PHASE_STORE(P0,P1,P2,P3)                                           \
    _Pragma("unroll")                                                      \
    for (int j = 0; j < 16; ++j) st[sw(pidx<P0,P1,P2,P3>(base, j))] = r[j];

// ---- the 8 phases of one sim14 layer (wire w <-> amplitude bit 11-w) ----
// Layer = RY ring (idx 0..11) fused with chainA (idx 12..23), then RY ring
// (24..35) fused with chainB (36..47). Groupings preserve gate ordering.

__device__ __forceinline__ void phA1(ull* st, const float2* c, int tid) {
    PHASE_LOAD(11, 0, 1, 2);
    gry<0>(r, c[0]);  gry<1>(r, c[11]); gry<2>(r, c[10]); gry<3>(r, c[9]);
    gcrx<1, 0>(r, c[12]); gcrx<2, 1>(r, c[13]); gcrx<3, 2>(r, c[14]);
    PHASE_STORE(11, 0, 1, 2);
}
// phA1 variant that reads the input state directly from GLOBAL memory
// (saves the staging STS + LDS round trip and one barrier).
__device__ __forceinline__ void phA1_ldg(ull* st, const ull* __restrict__ g,
                                         const float2* c, int tid) {
    uint32_t base = phase_base<11, 0, 1, 2>(tid);
    ull r[16];
#pragma unroll
    for (int j = 0; j < 16; ++j) r[j] = __ldg(&g[pidx<11, 0, 1, 2>(base, j)]);
    gry<0>(r, c[0]);  gry<1>(r, c[11]); gry<2>(r, c[10]); gry<3>(r, c[9]);
    gcrx<1, 0>(r, c[12]); gcrx<2, 1>(r, c[13]); gcrx<3, 2>(r, c[14]);
    PHASE_STORE(11, 0, 1, 2);
}
__device__ __forceinline__ void phA2(ull* st, const float2* c, int tid) {
    PHASE_LOAD(2, 3, 4, 5);
    gry<1>(r, c[8]); gry<2>(r, c[7]); gry<3>(r, c[6]);
    gcrx<1, 0>(r, c[15]); gcrx<2, 1>(r, c[16]); gcrx<3, 2>(r, c[17]);
    PHASE_STORE(2, 3, 4, 5);
}
__device__ __forceinline__ void phA3(ull* st, const float2* c, int tid) {
    PHASE_LOAD(5, 6, 7, 8);
    gry<1>(r, c[5]); gry<2>(r, c[4]); gry<3>(r, c[3]);
    gcrx<1, 0>(r, c[18]); gcrx<2, 1>(r, c[19]); gcrx<3, 2>(r, c[20]);
    PHASE_STORE(5, 6, 7, 8);
}
__device__ __forceinline__ void phA4(ull* st, const float2* c, int tid) {
    PHASE_LOAD(8, 9, 10, 11);
    gry<1>(r, c[2]); gry<2>(r, c[1]);
    gcrx<1, 0>(r, c[21]); gcrx<2, 1>(r, c[22]); gcrx<3, 2>(r, c[23]);
    PHASE_STORE(8, 9, 10, 11);
}
__device__ __forceinline__ void phB1(ull* st, const float2* c, int tid) {
    PHASE_LOAD(1, 0, 11, 10);
    gry<0>(r, c[34]); gry<1>(r, c[35]); gry<2>(r, c[24]); gry<3>(r, c[25]);
    gcrx<1, 0>(r, c[36]); gcrx<2, 1>(r, c[37]); gcrx<3, 2>(r, c[38]);
    PHASE_STORE(1, 0, 11, 10);
}
__device__ __forceinline__ void phB2(ull* st, const float2* c, int tid) {
    PHASE_LOAD(10, 9, 8, 7);
    gry<1>(r, c[26]); gry<2>(r, c[27]); gry<3>(r, c[28]);
    gcrx<1, 0>(r, c[39]); gcrx<2, 1>(r, c[40]); gcrx<3, 2>(r, c[41]);
    PHASE_STORE(10, 9, 8, 7);
}
__device__ __forceinline__ void phB3(ull* st, const float2* c, int tid) {
    PHASE_LOAD(7, 6, 5, 4);
    gry<1>(r, c[29]); gry<2>(r, c[30]); gry<3>(r, c[31]);
    gcrx<1, 0>(r, c[42]); gcrx<2, 1>(r, c[43]); gcrx<3, 2>(r, c[44]);
    PHASE_STORE(7, 6, 5, 4);
}
__device__ __forceinline__ void phB4(ull* st, const float2* c, int tid) {
    PHASE_LOAD(4, 3, 2, 1);
    gry<1>(r, c[32]); gry<2>(r, c[33]);
    gcrx<1, 0>(r, c[45]); gcrx<2, 1>(r, c[46]); gcrx<3, 2>(r, c[47]);
    PHASE_STORE(4, 3, 2, 1);
}

__device__ __forceinline__ void run_layer(ull* st, const float2* c, int tid) {
    phA1(st, c, tid); __syncthreads();
    phA2(st, c, tid); __syncthreads();
    phA3(st, c, tid); __syncthreads();
    phA4(st, c, tid); __syncthreads();
    phB1(st, c, tid); __syncthreads();
    phB2(st, c, tid); __syncthreads();
    phB3(st, c, tid); __syncthreads();
    phB4(st, c, tid); __syncthreads();
}

// ---------------------------------------------------------------------------
// Kernel 1 (merged prep): blocks [0, 5120): zero/init g_work.
//                         blocks [5120, 7168): param projection for bt.
// ---------------------------------------------------------------------------
#define INIT_BLKS ((DEGREE + 1) * BATCH * DIM / 256)   // 5120
__global__ void prep_kernel(const float* __restrict__ x,
                            const float* __restrict__ Wp,
                            const float* __restrict__ bp,
                            const float* __restrict__ qff) {
    if (blockIdx.x < INIT_BLKS) {
        uint32_t e = blockIdx.x * 256 + threadIdx.x;
        float2* flat = &g_work[0][0];
        uint32_t buf = e >> 18;
        uint32_t rem = e & 0x3FFFFu;
        float2 v = make_float2(0.f, 0.f);
        if (buf == 0 && (rem & (DIM - 1)) == 0) v.x = 1.f;
        flat[e] = v;
        return;
    }
    __shared__ float xr[FDIM];
    int bt = blockIdx.x - INIT_BLKS;   // 0..2047
    int r = threadIdx.x;               // 0..255 (only 0..95 produce)
    if (r < FDIM) xr[r] = x[bt * FDIM + r];
    __syncthreads();
    if (r < NROTS) {
        float acc = bp[r];
#pragma unroll
        for (int f = 0; f < FDIM; ++f) acc += xr[f] * Wp[r * FDIM + f];
        float sg = 1.0f / (1.0f + expf(-acc));
        float h = 3.14159265358979323846f * sg;   // theta/2 = pi * sigmoid
        float sv, cv; sincosf(h, &sv, &cv);
        g_cs[bt * NROTS + r] = make_float2(cv, sv);
        if (bt == 0 && r < QFFROTS) {
            float hq = 0.5f * qff[r];
            float sq, cq; sincosf(hq, &sq, &cq);
            g_csqff[r] = make_float2(cq, sq);
        }
    }
}

// ---------------------------------------------------------------------------
// Kernel 2: one polynomial degree. grid = 2048 (one CTA per (b,t)), 256 thr.
// 15 smem phases: phase 1 loads directly from global, final phase fused with
// mix+flush (red.global.add.v2.f32).
// ---------------------------------------------------------------------------
__global__ void __launch_bounds__(256, 4)
circuit_kernel(const ull* __restrict__ win, float2* __restrict__ wout,
               const float* __restrict__ mix_re, const float* __restrict__ mix_im) {
    extern __shared__ ull dsm[];
    ull* st = dsm;                            // DIM
    float2* cc = (float2*)(dsm + DIM);        // 96 coeffs + mix at [96]

    const int tid = threadIdx.x;
    const int b = blockIdx.x >> 5;
    const int t = blockIdx.x & 31;

    if (tid < NROTS) cc[tid] = g_cs[(b * TSTEPS + t) * NROTS + tid];
    if (tid == NROTS) cc[NROTS] = make_float2(mix_re[t], mix_im[t]);
    __syncthreads();

    // layer 0: phase 1 reads straight from global (no staging round trip)
    phA1_ldg(st, win + b * DIM, cc, tid); __syncthreads();
    phA2(st, cc, tid); __syncthreads();
    phA3(st, cc, tid); __syncthreads();
    phA4(st, cc, tid); __syncthreads();
    phB1(st, cc, tid); __syncthreads();
    phB2(st, cc, tid); __syncthreads();
    phB3(st, cc, tid); __syncthreads();
    phB4(st, cc, tid); __syncthreads();
    // layer 1: first 7 phases, last phase kept in registers
    const float2* c1 = cc + 48;
    phA1(st, c1, tid); __syncthreads();
    phA2(st, c1, tid); __syncthreads();
    phA3(st, c1, tid); __syncthreads();
    phA4(st, c1, tid); __syncthreads();
    phB1(st, c1, tid); __syncthreads();
    phB2(st, c1, tid); __syncthreads();
    phB3(st, c1, tid); __syncthreads();
    {   // phB4 without store: mix[t] * psi -> red.global directly
        PHASE_LOAD(4, 3, 2, 1);
        gry<1>(r, c1[32]); gry<2>(r, c1[33]);
        gcrx<1, 0>(r, c1[45]); gcrx<2, 1>(r, c1[46]); gcrx<3, 2>(r, c1[47]);
        float2 mx = cc[NROTS];
        const ull mr2 = dup2(mx.x);
        const ull mpm = pk2(-mx.y, mx.y);   // mul(mpm, swap(v)) = (-mi*vy, mi*vx)
#pragma unroll
        for (int j = 0; j < 16; ++j) {
            uint32_t i = pidx<4, 3, 2, 1>(base, j);
            ull v = f2fma(mr2, r[j], f2mul(mpm, swp(r[j])));
            red2(&wout[b * DIM + i], upk(v));
        }
    }
}

// ---------------------------------------------------------------------------
// Kernel 3: assemble acc, normalize, qff layer, Pauli expvals, output linear.
// grid = 64 (one CTA per batch), 256 threads.
// ---------------------------------------------------------------------------
__global__ void final_kernel(const float* __restrict__ poly,
                             const float* __restrict__ W_out,
                             const float* __restrict__ b_out,
                             float* __restrict__ out) {
    __shared__ ull st[DIM];
    __shared__ float red[37];            // [0..35] expvals, [36] sumsq
    const int tid = threadIdx.x;
    const int b = blockIdx.x;

    float p[DEGREE + 1];
#pragma unroll
    for (int d = 0; d <= DEGREE; ++d) p[d] = poly[d];
    float sabs = 0.f;
#pragma unroll
    for (int d = 0; d <= DEGREE; ++d) sabs += fabsf(p[d]);
    const float inv_s = 1.f / sabs;

    if (tid == 0) red[36] = 0.f;
    const ull* wflat = (const ull*)&g_work[0][0];
    float lsq = 0.f;
#pragma unroll
    for (int k = 0; k < 16; ++k) {
        int i = tid + 256 * k;
        ull v = 0ull;
#pragma unroll
        for (int d = 0; d <= DEGREE; ++d) {
            ull w = wflat[(size_t)d * (BATCH * DIM) + b * DIM + i];
            v = f2fma(dup2(p[d]), w, v);
        }
        v = f2mul(dup2(inv_s), v);
        st[sw((uint32_t)i)] = v;
        float2 vf = upk(v);
        lsq += vf.x * vf.x + vf.y * vf.y;
    }
#pragma unroll
    for (int o = 16; o > 0; o >>= 1) lsq += __shfl_xor_sync(0xffffffffu, lsq, o);
    if ((tid & 31) == 0) atomicAdd(&red[36], lsq);
    __syncthreads();

    const float f = 1.f / (sqrtf(red[36]) + 1e-9f);
    const ull f2 = dup2(f);
#pragma unroll
    for (int k = 0; k < 16; ++k) {
        int i = tid + 256 * k;
        uint32_t s_ = sw((uint32_t)i);
        st[s_] = f2mul(f2, st[s_]);
    }
    __syncthreads();

    run_layer(st, g_csqff, tid);     // qff: one sim14 layer

    if (tid < 36) red[tid] = 0.f;
    __syncthreads();

    float xx[NQ], yy[NQ], zz[NQ];
#pragma unroll
    for (int w = 0; w < NQ; ++w) { xx[w] = 0.f; yy[w] = 0.f; zz[w] = 0.f; }

#pragma unroll
    for (int k = 0; k < 16; ++k) {
        int i = tid + 256 * k;
        float2 a = upk(st[sw((uint32_t)i)]);
        float n2 = a.x * a.x + a.y * a.y;
#pragma unroll
        for (int w = 0; w < NQ; ++w) {
            int pbit = 11 - w;
            if (((i >> pbit) & 1) == 0) {
                float2 a1 = upk(st[sw((uint32_t)(i | (1 << pbit)))]);
                xx[w] += 2.f * (a.x * a1.x + a.y * a1.y);
                yy[w] += 2.f * (a.x * a1.y - a.y * a1.x);
                zz[w] += n2;
            } else {
                zz[w] -= n2;
            }
        }
    }
#pragma unroll
    for (int w = 0; w < NQ; ++w) {
        atomicAdd(&red[w], xx[w]);
        atomicAdd(&red[12 + w], yy[w]);
        atomicAdd(&red[24 + w], zz[w]);
    }
    __syncthreads();

    if (tid < ODIM) {
        float acc = b_out[tid];
#pragma unroll
        for (int j = 0; j < 36; ++j) acc += W_out[tid * 36 + j] * red[j];
        out[b * ODIM + tid] = acc;
    }
}

// ---------------------------------------------------------------------------
// Inputs (metadata order): x, W_proj, b_proj, poly_coeffs, mix_re, mix_im,
//                          qff_params, W_out, b_out.  Output: float32 [64,8].
// ---------------------------------------------------------------------------
extern "C" void kernel_launch(void* const* d_in, const int* in_sizes, int n_in,
                              void* d_out, int out_size) {
    (void)in_sizes; (void)n_in; (void)out_size;
    const float* x      = (const float*)d_in[0];
    const float* W_proj = (const float*)d_in[1];
    const float* b_proj = (const float*)d_in[2];
    const float* poly   = (const float*)d_in[3];
    const float* mix_re = (const float*)d_in[4];
    const float* mix_im = (const float*)d_in[5];
    const float* qff    = (const float*)d_in[6];
    const float* W_out  = (const float*)d_in[7];
    const float* b_out  = (const float*)d_in[8];
    float* out = (float*)d_out;

    cudaFuncSetAttribute(circuit_kernel,
                         cudaFuncAttributeMaxDynamicSharedMemorySize, CIRC_SMEM);

    prep_kernel<<<INIT_BLKS + BATCH * TSTEPS, 256>>>(x, W_proj, b_proj, qff);

    float2* w0;
    cudaGetSymbolAddress((void**)&w0, g_work);   // base of g_work
    float2* w1 = w0 + 1 * BATCH * DIM;
    float2* w2 = w0 + 2 * BATCH * DIM;
    float2* w3 = w0 + 3 * BATCH * DIM;
    float2* w4 = w0 + 4 * BATCH * DIM;

    circuit_kernel<<<NBLK_CIRC, 256, CIRC_SMEM>>>((const ull*)w0, w1, mix_re, mix_im);
    circuit_kernel<<<NBLK_CIRC, 256, CIRC_SMEM>>>((const ull*)w1, w2, mix_re, mix_im);
    circuit_kernel<<<NBLK_CIRC, 256, CIRC_SMEM>>>((const ull*)w2, w3, mix_re, mix_im);
    circuit_kernel<<<NBLK_CIRC, 256, CIRC_SMEM>>>((const ull*)w3, w4, mix_re, mix_im);

    final_kernel<<<BATCH, 256>>>(poly, W_out, b_out, out);
}

// round 11
// speedup vs baseline: 1.0337x; 1.0061x over previous
#include <cuda_runtime.h>
#include <cuda_bf16.h>
#include <math.h>
#include <stdint.h>

// ---------------------------------------------------------------------------
// QuantumTSTransformer: 12-qubit statevector sim, packed f32x2 arithmetic.
//   B=64, T=32, DEGREE=4, sim14 2 layers (96 rots), qff layer (48), DIM=4096.
// circuit_fused: ONE persistent kernel (592 CTAs, 4/SM) processes all
// 4*2048 (degree, b, t) circuits via a global ticket queue with per-(d,b)
// done-counters (red.global + threadfence + atomic signal / spin-wait).
// Per item: R7 core — state in 32KB dynamic smem as packed (re,im) b64,
// 8 phases/layer, 4 register-resident qubits (16 amps/thread, 256 thr,
// 64 regs). Final phase fuses mix[t]*psi and flushes via red.global.add.v2.
// ---------------------------------------------------------------------------

#define NQ       12
#define DIM      4096
#define BATCH    64
#define TSTEPS   32
#define NROTS    96
#define QFFROTS  48
#define DEGREE   4
#define FDIM     64
#define ODIM     8
#define NITEMS   (DEGREE * BATCH * TSTEPS)      // 8192
#define NPERS    592                            // 4 CTAs x 148 SMs
#define CIRC_SMEM (DIM * 8 + 1024)              // st + coeffs

typedef unsigned long long ull;

// Scratch (device globals: no allocation allowed)
__device__ float2 g_work[DEGREE + 1][BATCH * DIM];   // work_0=base, work_1..4
__device__ float2 g_cs[BATCH * TSTEPS * NROTS];      // (cos(h), sin(h)) per rot
__device__ float2 g_csqff[QFFROTS];
__device__ unsigned g_ticket;                        // work queue head
__device__ unsigned g_done[DEGREE][BATCH];           // producers-finished count

// ---------------- packed f32x2 helpers ----------------
__device__ __forceinline__ ull pk2(float x, float y) {
    ull r; asm("mov.b64 %0, {%1, %2};" : "=l"(r) : "f"(x), "f"(y)); return r;
}
__device__ __forceinline__ ull dup2(float x) { return pk2(x, x); }
__device__ __forceinline__ float2 upk(ull v) {
    float2 r; asm("mov.b64 {%0, %1}, %2;" : "=f"(r.x), "=f"(r.y) : "l"(v)); return r;
}
__device__ __forceinline__ ull swp(ull v) {   // (x,y) -> (y,x)
    ull r;
    asm("{\n\t.reg .b32 lo, hi;\n\tmov.b64 {lo, hi}, %1;\n\tmov.b64 %0, {hi, lo};\n\t}"
        : "=l"(r) : "l"(v));
    return r;
}
__device__ __forceinline__ ull f2mul(ull a, ull b) {
    ull r; asm("mul.rn.f32x2 %0, %1, %2;" : "=l"(r) : "l"(a), "l"(b)); return r;
}
__device__ __forceinline__ ull f2fma(ull a, ull b, ull c) {
    ull r; asm("fma.rn.f32x2 %0, %1, %2, %3;" : "=l"(r) : "l"(a), "l"(b), "l"(c)); return r;
}
__device__ __forceinline__ void red2(float2* p, float2 v) {
    asm volatile("red.global.add.v2.f32 [%0], {%1, %2};"
                 :: "l"(p), "f"(v.x), "f"(v.y) : "memory");
}

// smem slot swizzle: bijective, conflict-free for all phase patterns
__device__ __forceinline__ uint32_t sw(uint32_t i) { return i ^ ((i >> 4) & 0xFu); }

// base address: deposit 8 tid bits into the amplitude-index bits NOT in {P0..P3}
template<int P0, int P1, int P2, int P3>
__device__ __forceinline__ uint32_t phase_base(int tid) {
    constexpr uint32_t M = (1u << P0) | (1u << P1) | (1u << P2) | (1u << P3);
    uint32_t base = 0;
    int tb = 0;
#pragma unroll
    for (int pos = 0; pos < NQ; ++pos) {
        if (!((M >> pos) & 1u)) {
            base |= ((uint32_t)(tid >> tb) & 1u) << pos;
            ++tb;
        }
    }
    return base;
}

template<int P0, int P1, int P2, int P3>
__device__ __forceinline__ uint32_t pidx(uint32_t base, int j) {
    return base
        | ((j & 1) ? (1u << P0) : 0u)
        | ((j & 2) ? (1u << P1) : 0u)
        | ((j & 4) ? (1u << P2) : 0u)
        | ((j & 8) ? (1u << P3) : 0u);
}

// RY on register-bit RB:  a0' = c a0 - s a1 ; a1' = s a0 + c a1  (componentwise)
template<int RB>
__device__ __forceinline__ void gry(ull* r, float2 cs) {
    const ull c2 = dup2(cs.x), s2 = dup2(cs.y), ns2 = dup2(-cs.y);
#pragma unroll
    for (int j = 0; j < 16; ++j) {
        if (!(j & (1 << RB))) {
            ull a0 = r[j], a1 = r[j | (1 << RB)];
            r[j]            = f2fma(c2, a0, f2mul(ns2, a1));
            r[j | (1 << RB)] = f2fma(s2, a0, f2mul(c2, a1));
        }
    }
}

// CRX: control RBC==1, target RBT.  a0' = c a0 - i s a1 ; a1' = c a1 - i s a0.
//  -i s v = (s*v.y, -s*v.x) = mul((s,-s), swap(v))
template<int RBC, int RBT>
__device__ __forceinline__ void gcrx(ull* r, float2 cs) {
    const ull c2 = dup2(cs.x);
    const ull spm = pk2(cs.y, -cs.y);
#pragma unroll
    for (int j = 0; j < 16; ++j) {
        if ((j & (1 << RBC)) && !(j & (1 << RBT))) {
            ull a0 = r[j], a1 = r[j | (1 << RBT)];
            r[j]             = f2fma(c2, a0, f2mul(spm, swp(a1)));
            r[j | (1 << RBT)] = f2fma(c2, a1, f2mul(spm, swp(a0)));
        }
    }
}

#define PHASE_LOAD(P0,P1,P2,P3)                                            \
    uint32_t base = phase_base<P0,P1,P2,P3>(tid);                          \
    ull r[16];                                                             \
    _Pragma("unroll")                                                      \
    for (int j = 0; j < 16; ++j) r[j] = st[sw(pidx<P0,P1,P2,P3>(base, j))];

#define PHASE_STORE(P0,P1,P2,P3)                                           \
    _Pragma("unroll")                                                      \
    for (int j = 0; j < 16; ++j) st[sw(pidx<P0,P1,P2,P3>(base, j))] = r[j];

// ---- the 8 phases of one sim14 layer (wire w <-> amplitude bit 11-w) ----
// Layer = RY ring (idx 0..11) fused with chainA (idx 12..23), then RY ring
// (24..35) fused with chainB (36..47). Groupings preserve gate ordering.

__device__ __forceinline__ void phA1(ull* st, const float2* c, int tid) {
    PHASE_LOAD(11, 0, 1, 2);
    gry<0>(r, c[0]);  gry<1>(r, c[11]); gry<2>(r, c[10]); gry<3>(r, c[9]);
    gcrx<1, 0>(r, c[12]); gcrx<2, 1>(r, c[13]); gcrx<3, 2>(r, c[14]);
    PHASE_STORE(11, 0, 1, 2);
}
__device__ __forceinline__ void phA2(ull* st, const float2* c, int tid) {
    PHASE_LOAD(2, 3, 4, 5);
    gry<1>(r, c[8]); gry<2>(r, c[7]); gry<3>(r, c[6]);
    gcrx<1, 0>(r, c[15]); gcrx<2, 1>(r, c[16]); gcrx<3, 2>(r, c[17]);
    PHASE_STORE(2, 3, 4, 5);
}
__device__ __forceinline__ void phA3(ull* st, const float2* c, int tid) {
    PHASE_LOAD(5, 6, 7, 8);
    gry<1>(r, c[5]); gry<2>(r, c[4]); gry<3>(r, c[3]);
    gcrx<1, 0>(r, c[18]); gcrx<2, 1>(r, c[19]); gcrx<3, 2>(r, c[20]);
    PHASE_STORE(5, 6, 7, 8);
}
__device__ __forceinline__ void phA4(ull* st, const float2* c, int tid) {
    PHASE_LOAD(8, 9, 10, 11);
    gry<1>(r, c[2]); gry<2>(r, c[1]);
    gcrx<1, 0>(r, c[21]); gcrx<2, 1>(r, c[22]); gcrx<3, 2>(r, c[23]);
    PHASE_STORE(8, 9, 10, 11);
}
__device__ __forceinline__ void phB1(ull* st, const float2* c, int tid) {
    PHASE_LOAD(1, 0, 11, 10);
    gry<0>(r, c[34]); gry<1>(r, c[35]); gry<2>(r, c[24]); gry<3>(r, c[25]);
    gcrx<1, 0>(r, c[36]); gcrx<2, 1>(r, c[37]); gcrx<3, 2>(r, c[38]);
    PHASE_STORE(1, 0, 11, 10);
}
__device__ __forceinline__ void phB2(ull* st, const float2* c, int tid) {
    PHASE_LOAD(10, 9, 8, 7);
    gry<1>(r, c[26]); gry<2>(r, c[27]); gry<3>(r, c[28]);
    gcrx<1, 0>(r, c[39]); gcrx<2, 1>(r, c[40]); gcrx<3, 2>(r, c[41]);
    PHASE_STORE(10, 9, 8, 7);
}
__device__ __forceinline__ void phB3(ull* st, const float2* c, int tid) {
    PHASE_LOAD(7, 6, 5, 4);
    gry<1>(r, c[29]); gry<2>(r, c[30]); gry<3>(r, c[31]);
    gcrx<1, 0>(r, c[42]); gcrx<2, 1>(r, c[43]); gcrx<3, 2>(r, c[44]);
    PHASE_STORE(7, 6, 5, 4);
}
__device__ __forceinline__ void phB4(ull* st, const float2* c, int tid) {
    PHASE_LOAD(4, 3, 2, 1);
    gry<1>(r, c[32]); gry<2>(r, c[33]);
    gcrx<1, 0>(r, c[45]); gcrx<2, 1>(r, c[46]); gcrx<3, 2>(r, c[47]);
    PHASE_STORE(4, 3, 2, 1);
}

__device__ __forceinline__ void run_layer(ull* st, const float2* c, int tid) {
    phA1(st, c, tid); __syncthreads();
    phA2(st, c, tid); __syncthreads();
    phA3(st, c, tid); __syncthreads();
    phA4(st, c, tid); __syncthreads();
    phB1(st, c, tid); __syncthreads();
    phB2(st, c, tid); __syncthreads();
    phB3(st, c, tid); __syncthreads();
    phB4(st, c, tid); __syncthreads();
}

// ---------------------------------------------------------------------------
// Kernel 1 (merged prep): blocks [0, 5120): zero/init g_work (+ queue state).
//                         blocks [5120, 7168): param projection for bt.
// ---------------------------------------------------------------------------
#define INIT_BLKS ((DEGREE + 1) * BATCH * DIM / 256)   // 5120
__global__ void prep_kernel(const float* __restrict__ x,
                            const float* __restrict__ Wp,
                            const float* __restrict__ bp,
                            const float* __restrict__ qff) {
    if (blockIdx.x < INIT_BLKS) {
        uint32_t e = blockIdx.x * 256 + threadIdx.x;
        if (blockIdx.x == 0) {                 // reset queue + done counters
            if (threadIdx.x == 0) g_ticket = 0u;
            if (threadIdx.x < DEGREE * BATCH)
                (&g_done[0][0])[threadIdx.x] = 0u;
        }
        float2* flat = &g_work[0][0];
        uint32_t buf = e >> 18;
        uint32_t rem = e & 0x3FFFFu;
        float2 v = make_float2(0.f, 0.f);
        if (buf == 0 && (rem & (DIM - 1)) == 0) v.x = 1.f;
        flat[e] = v;
        return;
    }
    __shared__ float xr[FDIM];
    int bt = blockIdx.x - INIT_BLKS;   // 0..2047
    int r = threadIdx.x;               // 0..255 (only 0..95 produce)
    if (r < FDIM) xr[r] = x[bt * FDIM + r];
    __syncthreads();
    if (r < NROTS) {
        float acc = bp[r];
#pragma unroll
        for (int f = 0; f < FDIM; ++f) acc += xr[f] * Wp[r * FDIM + f];
        float sg = 1.0f / (1.0f + expf(-acc));
        float h = 3.14159265358979323846f * sg;   // theta/2 = pi * sigmoid
        float sv, cv; sincosf(h, &sv, &cv);
        g_cs[bt * NROTS + r] = make_float2(cv, sv);
        if (bt == 0 && r < QFFROTS) {
            float hq = 0.5f * qff[r];
            float sq, cq; sincosf(hq, &sq, &cq);
            g_csqff[r] = make_float2(cq, sq);
        }
    }
}

// ---------------------------------------------------------------------------
// Kernel 2: persistent fused circuit kernel. 592 CTAs pull (d, b, t) items
// off a ticket queue; per-(d,b) done counters gate degree d -> d+1.
// ---------------------------------------------------------------------------
__global__ void __launch_bounds__(256, 4)
circuit_fused(const float* __restrict__ mix_re, const float* __restrict__ mix_im) {
    extern __shared__ ull dsm[];
    ull* st = dsm;                            // DIM
    float2* cc = (float2*)(dsm + DIM);        // 96 coeffs + mix at [96]
    __shared__ unsigned s_ticket;

    const int tid = threadIdx.x;

    for (;;) {
        __syncthreads();                      // protect st/cc/s_ticket reuse
        if (tid == 0) s_ticket = atomicAdd(&g_ticket, 1u);
        __syncthreads();
        const unsigned item = s_ticket;
        if (item >= NITEMS) break;
        const int d  = item >> 11;            // 0..3
        const int bt = item & 2047;
        const int b  = bt >> 5;
        const int t  = bt & 31;

        // wait for all 32 producers of work[d] for this b (d=0: ready)
        if (d > 0 && tid == 0) {
            while (atomicAdd(&g_done[d - 1][b], 0u) < (unsigned)TSTEPS)
                __nanosleep(128);
        }
        __syncthreads();
        __threadfence();                      // acquire: order wait before loads

        const ull* win = (const ull*)&g_work[d][b * DIM];
        float2* wout = &g_work[d + 1][b * DIM];

        // stage input state + coefficients
#pragma unroll
        for (int k = 0; k < 16; ++k) {
            int i = tid + 256 * k;
            st[sw((uint32_t)i)] = win[i];
        }
        if (tid < NROTS) cc[tid] = g_cs[(b * TSTEPS + t) * NROTS + tid];
        if (tid == NROTS) cc[NROTS] = make_float2(mix_re[t], mix_im[t]);
        __syncthreads();

        run_layer(st, cc, tid);               // layer 0 (8 phases)
        const float2* c1 = cc + 48;
        phA1(st, c1, tid); __syncthreads();
        phA2(st, c1, tid); __syncthreads();
        phA3(st, c1, tid); __syncthreads();
        phA4(st, c1, tid); __syncthreads();
        phB1(st, c1, tid); __syncthreads();
        phB2(st, c1, tid); __syncthreads();
        phB3(st, c1, tid); __syncthreads();
        {   // phB4 without store: mix[t] * psi -> red.global directly
            PHASE_LOAD(4, 3, 2, 1);
            gry<1>(r, c1[32]); gry<2>(r, c1[33]);
            gcrx<1, 0>(r, c1[45]); gcrx<2, 1>(r, c1[46]); gcrx<3, 2>(r, c1[47]);
            float2 mx = cc[NROTS];
            const ull mr2 = dup2(mx.x);
            const ull mpm = pk2(-mx.y, mx.y);
#pragma unroll
            for (int j = 0; j < 16; ++j) {
                uint32_t i = pidx<4, 3, 2, 1>(base, j);
                ull v = f2fma(mr2, r[j], f2mul(mpm, swp(r[j])));
                red2(&wout[i], upk(v));
            }
        }
        // release: make reds visible, then signal completion
        __threadfence();
        __syncthreads();
        if (tid == 0) atomicAdd(&g_done[d][b], 1u);
    }
}

// ---------------------------------------------------------------------------
// Kernel 3: assemble acc, normalize, qff layer, Pauli expvals, output linear.
// grid = 64 (one CTA per batch), 256 threads.
// ---------------------------------------------------------------------------
__global__ void final_kernel(const float* __restrict__ poly,
                             const float* __restrict__ W_out,
                             const float* __restrict__ b_out,
                             float* __restrict__ out) {
    __shared__ ull st[DIM];
    __shared__ float red[37];            // [0..35] expvals, [36] sumsq
    const int tid = threadIdx.x;
    const int b = blockIdx.x;

    float p[DEGREE + 1];
#pragma unroll
    for (int d = 0; d <= DEGREE; ++d) p[d] = poly[d];
    float sabs = 0.f;
#pragma unroll
    for (int d = 0; d <= DEGREE; ++d) sabs += fabsf(p[d]);
    const float inv_s = 1.f / sabs;

    if (tid == 0) red[36] = 0.f;
    const ull* wflat = (const ull*)&g_work[0][0];
    float lsq = 0.f;
#pragma unroll
    for (int k = 0; k < 16; ++k) {
        int i = tid + 256 * k;
        ull v = 0ull;
#pragma unroll
        for (int d = 0; d <= DEGREE; ++d) {
            ull w = wflat[(size_t)d * (BATCH * DIM) + b * DIM + i];
            v = f2fma(dup2(p[d]), w, v);
        }
        v = f2mul(dup2(inv_s), v);
        st[sw((uint32_t)i)] = v;
        float2 vf = upk(v);
        lsq += vf.x * vf.x + vf.y * vf.y;
    }
#pragma unroll
    for (int o = 16; o > 0; o >>= 1) lsq += __shfl_xor_sync(0xffffffffu, lsq, o);
    if ((tid & 31) == 0) atomicAdd(&red[36], lsq);
    __syncthreads();

    const float f = 1.f / (sqrtf(red[36]) + 1e-9f);
    const ull f2 = dup2(f);
#pragma unroll
    for (int k = 0; k < 16; ++k) {
        int i = tid + 256 * k;
        uint32_t s_ = sw((uint32_t)i);
        st[s_] = f2mul(f2, st[s_]);
    }
    __syncthreads();

    run_layer(st, g_csqff, tid);     // qff: one sim14 layer

    if (tid < 36) red[tid] = 0.f;
    __syncthreads();

    float xx[NQ], yy[NQ], zz[NQ];
#pragma unroll
    for (int w = 0; w < NQ; ++w) { xx[w] = 0.f; yy[w] = 0.f; zz[w] = 0.f; }

#pragma unroll
    for (int k = 0; k < 16; ++k) {
        int i = tid + 256 * k;
        float2 a = upk(st[sw((uint32_t)i)]);
        float n2 = a.x * a.x + a.y * a.y;
#pragma unroll
        for (int w = 0; w < NQ; ++w) {
            int pbit = 11 - w;
            if (((i >> pbit) & 1) == 0) {
                float2 a1 = upk(st[sw((uint32_t)(i | (1 << pbit)))]);
                xx[w] += 2.f * (a.x * a1.x + a.y * a1.y);
                yy[w] += 2.f * (a.x * a1.y - a.y * a1.x);
                zz[w] += n2;
            } else {
                zz[w] -= n2;
            }
        }
    }
#pragma unroll
    for (int w = 0; w < NQ; ++w) {
        atomicAdd(&red[w], xx[w]);
        atomicAdd(&red[12 + w], yy[w]);
        atomicAdd(&red[24 + w], zz[w]);
    }
    __syncthreads();

    if (tid < ODIM) {
        float acc = b_out[tid];
#pragma unroll
        for (int j = 0; j < 36; ++j) acc += W_out[tid * 36 + j] * red[j];
        out[b * ODIM + tid] = acc;
    }
}

// ---------------------------------------------------------------------------
// Inputs (metadata order): x, W_proj, b_proj, poly_coeffs, mix_re, mix_im,
//                          qff_params, W_out, b_out.  Output: float32 [64,8].
// ---------------------------------------------------------------------------
extern "C" void kernel_launch(void* const* d_in, const int* in_sizes, int n_in,
                              void* d_out, int out_size) {
    (void)in_sizes; (void)n_in; (void)out_size;
    const float* x      = (const float*)d_in[0];
    const float* W_proj = (const float*)d_in[1];
    const float* b_proj = (const float*)d_in[2];
    const float* poly   = (const float*)d_in[3];
    const float* mix_re = (const float*)d_in[4];
    const float* mix_im = (const float*)d_in[5];
    const float* qff    = (const float*)d_in[6];
    const float* W_out  = (const float*)d_in[7];
    const float* b_out  = (const float*)d_in[8];
    float* out = (float*)d_out;

    cudaFuncSetAttribute(circuit_fused,
                         cudaFuncAttributeMaxDynamicSharedMemorySize, CIRC_SMEM);

    prep_kernel<<<INIT_BLKS + BATCH * TSTEPS, 256>>>(x, W_proj, b_proj, qff);
    circuit_fused<<<NPERS, 256, CIRC_SMEM>>>(mix_re, mix_im);
    final_kernel<<<BATCH, 256>>>(poly, W_out, b_out, out);
}

// round 12
// speedup vs baseline: 1.1080x; 1.0719x over previous
#include <cuda_runtime.h>
#include <cuda_bf16.h>
#include <math.h>
#include <stdint.h>

// ---------------------------------------------------------------------------
// QuantumTSTransformer: 12-qubit statevector sim, packed f32x2 arithmetic.
//   B=64, T=32, DEGREE=4, sim14 2 layers (96 rots), qff layer (48), DIM=4096.
// circuit_kernel (R7 core, best known): one CTA per (b,t); state in 32KB
// dynamic smem as packed (re,im) b64; 8 phases/layer, 4 register-resident
// qubits (16 amps/thread, 256 thr, 64 regs, 4 CTAs/SM). Final phase fuses
// mix[t]*psi, flushes via red.global.add.v2.f32.
// prep split into wide-vectorized init + MUFU param kernels (R11).
// ---------------------------------------------------------------------------

#define NQ       12
#define DIM      4096
#define BATCH    64
#define TSTEPS   32
#define NROTS    96
#define QFFROTS  48
#define DEGREE   4
#define FDIM     64
#define ODIM     8
#define NBLK_CIRC (BATCH * TSTEPS)              // 2048
#define CIRC_SMEM (DIM * 8 + 1024)              // st + coeffs

typedef unsigned long long ull;

// Scratch (device globals: no allocation allowed)
__device__ float2 g_work[DEGREE + 1][BATCH * DIM];   // work_0=base, work_1..4
__device__ float2 g_cs[BATCH * TSTEPS * NROTS];      // (cos(h), sin(h)) per rot
__device__ float2 g_csqff[QFFROTS];

// ---------------- packed f32x2 helpers ----------------
__device__ __forceinline__ ull pk2(float x, float y) {
    ull r; asm("mov.b64 %0, {%1, %2};" : "=l"(r) : "f"(x), "f"(y)); return r;
}
__device__ __forceinline__ ull dup2(float x) { return pk2(x, x); }
__device__ __forceinline__ float2 upk(ull v) {
    float2 r; asm("mov.b64 {%0, %1}, %2;" : "=f"(r.x), "=f"(r.y) : "l"(v)); return r;
}
__device__ __forceinline__ ull swp(ull v) {   // (x,y) -> (y,x)
    ull r;
    asm("{\n\t.reg .b32 lo, hi;\n\tmov.b64 {lo, hi}, %1;\n\tmov.b64 %0, {hi, lo};\n\t}"
        : "=l"(r) : "l"(v));
    return r;
}
__device__ __forceinline__ ull f2mul(ull a, ull b) {
    ull r; asm("mul.rn.f32x2 %0, %1, %2;" : "=l"(r) : "l"(a), "l"(b)); return r;
}
__device__ __forceinline__ ull f2fma(ull a, ull b, ull c) {
    ull r; asm("fma.rn.f32x2 %0, %1, %2, %3;" : "=l"(r) : "l"(a), "l"(b), "l"(c)); return r;
}
__device__ __forceinline__ void red2(float2* p, float2 v) {
    asm volatile("red.global.add.v2.f32 [%0], {%1, %2};"
                 :: "l"(p), "f"(v.x), "f"(v.y) : "memory");
}

// smem slot swizzle: bijective, conflict-free for all phase patterns
__device__ __forceinline__ uint32_t sw(uint32_t i) { return i ^ ((i >> 4) & 0xFu); }

// base address: deposit 8 tid bits into the amplitude-index bits NOT in {P0..P3}
template<int P0, int P1, int P2, int P3>
__device__ __forceinline__ uint32_t phase_base(int tid) {
    constexpr uint32_t M = (1u << P0) | (1u << P1) | (1u << P2) | (1u << P3);
    uint32_t base = 0;
    int tb = 0;
#pragma unroll
    for (int pos = 0; pos < NQ; ++pos) {
        if (!((M >> pos) & 1u)) {
            base |= ((uint32_t)(tid >> tb) & 1u) << pos;
            ++tb;
        }
    }
    return base;
}

template<int P0, int P1, int P2, int P3>
__device__ __forceinline__ uint32_t pidx(uint32_t base, int j) {
    return base
        | ((j & 1) ? (1u << P0) : 0u)
        | ((j & 2) ? (1u << P1) : 0u)
        | ((j & 4) ? (1u << P2) : 0u)
        | ((j & 8) ? (1u << P3) : 0u);
}

// RY on register-bit RB:  a0' = c a0 - s a1 ; a1' = s a0 + c a1  (componentwise)
template<int RB>
__device__ __forceinline__ void gry(ull* r, float2 cs) {
    const ull c2 = dup2(cs.x), s2 = dup2(cs.y), ns2 = dup2(-cs.y);
#pragma unroll
    for (int j = 0; j < 16; ++j) {
        if (!(j & (1 << RB))) {
            ull a0 = r[j], a1 = r[j | (1 << RB)];
            r[j]            = f2fma(c2, a0, f2mul(ns2, a1));
            r[j | (1 << RB)] = f2fma(s2, a0, f2mul(c2, a1));
        }
    }
}

// CRX: control RBC==1, target RBT.  a0' = c a0 - i s a1 ; a1' = c a1 - i s a0.
//  -i s v = (s*v.y, -s*v.x) = mul((s,-s), swap(v))
template<int RBC, int RBT>
__device__ __forceinline__ void gcrx(ull* r, float2 cs) {
    const ull c2 = dup2(cs.x);
    const ull spm = pk2(cs.y, -cs.y);
#pragma unroll
    for (int j = 0; j < 16; ++j) {
        if ((j & (1 << RBC)) && !(j & (1 << RBT))) {
            ull a0 = r[j], a1 = r[j | (1 << RBT)];
            r[j]             = f2fma(c2, a0, f2mul(spm, swp(a1)));
            r[j | (1 << RBT)] = f2fma(c2, a1, f2mul(spm, swp(a0)));
        }
    }
}

#define PHASE_LOAD(P0,P1,P2,P3)                                            \
    uint32_t base = phase_base<P0,P1,P2,P3>(tid);                          \
    ull r[16];                                                             \
    _Pragma("unroll")                                                      \
    for (int j = 0; j < 16; ++j) r[j] = st[sw(pidx<P0,P1,P2,P3>(base, j))];

#define PHASE_STORE(P0,P1,P2,P3)                                           \
    _Pragma("unroll")                                                      \
    for (int j = 0; j < 16; ++j) st[sw(pidx<P0,P1,P2,P3>(base, j))] = r[j];

// ---- the 8 phases of one sim14 layer (wire w <-> amplitude bit 11-w) ----
// Layer = RY ring (idx 0..11) fused with chainA (idx 12..23), then RY ring
// (24..35) fused with chainB (36..47). Groupings preserve gate ordering.

__device__ __forceinline__ void phA1(ull* st, const float2* c, int tid) {
    PHASE_LOAD(11, 0, 1, 2);
    gry<0>(r, c[0]);  gry<1>(r, c[11]); gry<2>(r, c[10]); gry<3>(r, c[9]);
    gcrx<1, 0>(r, c[12]); gcrx<2, 1>(r, c[13]); gcrx<3, 2>(r, c[14]);
    PHASE_STORE(11, 0, 1, 2);
}
__device__ __forceinline__ void phA2(ull* st, const float2* c, int tid) {
    PHASE_LOAD(2, 3, 4, 5);
    gry<1>(r, c[8]); gry<2>(r, c[7]); gry<3>(r, c[6]);
    gcrx<1, 0>(r, c[15]); gcrx<2, 1>(r, c[16]); gcrx<3, 2>(r, c[17]);
    PHASE_STORE(2, 3, 4, 5);
}
__device__ __forceinline__ void phA3(ull* st, const float2* c, int tid) {
    PHASE_LOAD(5, 6, 7, 8);
    gry<1>(r, c[5]); gry<2>(r, c[4]); gry<3>(r, c[3]);
    gcrx<1, 0>(r, c[18]); gcrx<2, 1>(r, c[19]); gcrx<3, 2>(r, c[20]);
    PHASE_STORE(5, 6, 7, 8);
}
__device__ __forceinline__ void phA4(ull* st, const float2* c, int tid) {
    PHASE_LOAD(8, 9, 10, 11);
    gry<1>(r, c[2]); gry<2>(r, c[1]);
    gcrx<1, 0>(r, c[21]); gcrx<2, 1>(r, c[22]); gcrx<3, 2>(r, c[23]);
    PHASE_STORE(8, 9, 10, 11);
}
__device__ __forceinline__ void phB1(ull* st, const float2* c, int tid) {
    PHASE_LOAD(1, 0, 11, 10);
    gry<0>(r, c[34]); gry<1>(r, c[35]); gry<2>(r, c[24]); gry<3>(r, c[25]);
    gcrx<1, 0>(r, c[36]); gcrx<2, 1>(r, c[37]); gcrx<3, 2>(r, c[38]);
    PHASE_STORE(1, 0, 11, 10);
}
__device__ __forceinline__ void phB2(ull* st, const float2* c, int tid) {
    PHASE_LOAD(10, 9, 8, 7);
    gry<1>(r, c[26]); gry<2>(r, c[27]); gry<3>(r, c[28]);
    gcrx<1, 0>(r, c[39]); gcrx<2, 1>(r, c[40]); gcrx<3, 2>(r, c[41]);
    PHASE_STORE(10, 9, 8, 7);
}
__device__ __forceinline__ void phB3(ull* st, const float2* c, int tid) {
    PHASE_LOAD(7, 6, 5, 4);
    gry<1>(r, c[29]); gry<2>(r, c[30]); gry<3>(r, c[31]);
    gcrx<1, 0>(r, c[42]); gcrx<2, 1>(r, c[43]); gcrx<3, 2>(r, c[44]);
    PHASE_STORE(7, 6, 5, 4);
}
__device__ __forceinline__ void phB4(ull* st, const float2* c, int tid) {
    PHASE_LOAD(4, 3, 2, 1);
    gry<1>(r, c[32]); gry<2>(r, c[33]);
    gcrx<1, 0>(r, c[45]); gcrx<2, 1>(r, c[46]); gcrx<3, 2>(r, c[47]);
    PHASE_STORE(4, 3, 2, 1);
}

__device__ __forceinline__ void run_layer(ull* st, const float2* c, int tid) {
    phA1(st, c, tid); __syncthreads();
    phA2(st, c, tid); __syncthreads();
    phA3(st, c, tid); __syncthreads();
    phA4(st, c, tid); __syncthreads();
    phB1(st, c, tid); __syncthreads();
    phB2(st, c, tid); __syncthreads();
    phB3(st, c, tid); __syncthreads();
    phB4(st, c, tid); __syncthreads();
}

// ---------------------------------------------------------------------------
// Kernel 1a: wide-vectorized init of g_work. 640 blocks x 256 threads,
// each thread writes 4 x float4 (64B). Base state ones placed inline.
// ---------------------------------------------------------------------------
__global__ void init_kernel() {
    uint32_t tgid = blockIdx.x * 256 + threadIdx.x;   // 0 .. 163839
    uint32_t c0 = tgid * 8;                            // first float2 index
    float4* p = (float4*)&g_work[0][0];
    float4 z = make_float4(0.f, 0.f, 0.f, 0.f);
    // base-state one: buffer 0, (index % DIM)==0. c0 is 8-aligned so only
    // the first float2 of this thread's span can qualify.
    bool one = (c0 < (uint32_t)(BATCH * DIM)) && ((c0 & (DIM - 1)) == 0);
    float4 z0 = z;
    if (one) z0.x = 1.f;
    p[tgid * 4 + 0] = z0;
    p[tgid * 4 + 1] = z;
    p[tgid * 4 + 2] = z;
    p[tgid * 4 + 3] = z;
}

// ---------------------------------------------------------------------------
// Kernel 1b: param projection. 2048 blocks x 96 threads; float4 dot products,
// MUFU __expf/__sincosf (tolerance 1e-3; error ~1e-6 acceptable).
// ---------------------------------------------------------------------------
__global__ void param_kernel(const float* __restrict__ x,
                             const float* __restrict__ Wp,
                             const float* __restrict__ bp,
                             const float* __restrict__ qff) {
    __shared__ float4 xr[FDIM / 4];            // 16 float4
    int bt = blockIdx.x;                       // 0..2047
    int r = threadIdx.x;                       // 0..95
    if (r < FDIM / 4) xr[r] = ((const float4*)(x + bt * FDIM))[r];
    __syncthreads();
    const float4* wrow = (const float4*)(Wp + r * FDIM);
    float acc = bp[r];
#pragma unroll
    for (int f = 0; f < FDIM / 4; ++f) {
        float4 xv = xr[f], wv = wrow[f];
        acc += xv.x * wv.x + xv.y * wv.y + xv.z * wv.z + xv.w * wv.w;
    }
    float sg = 1.0f / (1.0f + __expf(-acc));
    float h = 3.14159265358979323846f * sg;    // theta/2 = pi * sigmoid
    float sv, cv; __sincosf(h, &sv, &cv);
    g_cs[bt * NROTS + r] = make_float2(cv, sv);
    if (bt == 0 && r < QFFROTS) {
        float hq = 0.5f * qff[r];
        float sq, cq; __sincosf(hq, &sq, &cq);
        g_csqff[r] = make_float2(cq, sq);
    }
}

// ---------------------------------------------------------------------------
// Kernel 2: one polynomial degree. grid = 2048 (one CTA per (b,t)), 256 thr.
// ---------------------------------------------------------------------------
__global__ void __launch_bounds__(256, 4)
circuit_kernel(const ull* __restrict__ win, float2* __restrict__ wout,
               const float* __restrict__ mix_re, const float* __restrict__ mix_im) {
    extern __shared__ ull dsm[];
    ull* st = dsm;                            // DIM
    float2* cc = (float2*)(dsm + DIM);        // 96 coeffs + mix at [96]

    const int tid = threadIdx.x;
    const int b = blockIdx.x >> 5;
    const int t = blockIdx.x & 31;

    // load input state (64-bit, coalesced; sw touches only bits 0..3)
#pragma unroll
    for (int k = 0; k < 16; ++k) {
        int i = tid + 256 * k;
        st[sw((uint32_t)i)] = win[b * DIM + i];
    }
    if (tid < NROTS) cc[tid] = g_cs[(b * TSTEPS + t) * NROTS + tid];
    if (tid == NROTS) cc[NROTS] = make_float2(mix_re[t], mix_im[t]);
    __syncthreads();

    run_layer(st, cc, tid);               // layer 0 (8 phases)
    const float2* c1 = cc + 48;
    // layer 1: first 7 phases, last phase kept in registers
    phA1(st, c1, tid); __syncthreads();
    phA2(st, c1, tid); __syncthreads();
    phA3(st, c1, tid); __syncthreads();
    phA4(st, c1, tid); __syncthreads();
    phB1(st, c1, tid); __syncthreads();
    phB2(st, c1, tid); __syncthreads();
    phB3(st, c1, tid); __syncthreads();
    {   // phB4 without store: mix[t] * psi -> red.global directly
        PHASE_LOAD(4, 3, 2, 1);
        gry<1>(r, c1[32]); gry<2>(r, c1[33]);
        gcrx<1, 0>(r, c1[45]); gcrx<2, 1>(r, c1[46]); gcrx<3, 2>(r, c1[47]);
        float2 mx = cc[NROTS];
        const ull mr2 = dup2(mx.x);
        const ull mpm = pk2(-mx.y, mx.y);   // mul(mpm, swap(v)) = (-mi*vy, mi*vx)
#pragma unroll
        for (int j = 0; j < 16; ++j) {
            uint32_t i = pidx<4, 3, 2, 1>(base, j);
            ull v = f2fma(mr2, r[j], f2mul(mpm, swp(r[j])));
            red2(&wout[b * DIM + i], upk(v));
        }
    }
}

// ---------------------------------------------------------------------------
// Kernel 3: assemble acc, normalize, qff layer, Pauli expvals, output linear.
// grid = 64 (one CTA per batch), 256 threads.
// ---------------------------------------------------------------------------
__global__ void final_kernel(const float* __restrict__ poly,
                             const float* __restrict__ W_out,
                             const float* __restrict__ b_out,
                             float* __restrict__ out) {
    __shared__ ull st[DIM];
    __shared__ float red[37];            // [0..35] expvals, [36] sumsq
    const int tid = threadIdx.x;
    const int b = blockIdx.x;

    float p[DEGREE + 1];
#pragma unroll
    for (int d = 0; d <= DEGREE; ++d) p[d] = poly[d];
    float sabs = 0.f;
#pragma unroll
    for (int d = 0; d <= DEGREE; ++d) sabs += fabsf(p[d]);
    const float inv_s = 1.f / sabs;

    if (tid == 0) red[36] = 0.f;
    const ull* wflat = (const ull*)&g_work[0][0];
    float lsq = 0.f;
#pragma unroll
    for (int k = 0; k < 16; ++k) {
        int i = tid + 256 * k;
        ull v = 0ull;
#pragma unroll
        for (int d = 0; d <= DEGREE; ++d) {
            ull w = wflat[(size_t)d * (BATCH * DIM) + b * DIM + i];
            v = f2fma(dup2(p[d]), w, v);
        }
        v = f2mul(dup2(inv_s), v);
        st[sw((uint32_t)i)] = v;
        float2 vf = upk(v);
        lsq += vf.x * vf.x + vf.y * vf.y;
    }
#pragma unroll
    for (int o = 16; o > 0; o >>= 1) lsq += __shfl_xor_sync(0xffffffffu, lsq, o);
    if ((tid & 31) == 0) atomicAdd(&red[36], lsq);
    __syncthreads();

    const float f = 1.f / (sqrtf(red[36]) + 1e-9f);
    const ull f2 = dup2(f);
#pragma unroll
    for (int k = 0; k < 16; ++k) {
        int i = tid + 256 * k;
        uint32_t s_ = sw((uint32_t)i);
        st[s_] = f2mul(f2, st[s_]);
    }
    __syncthreads();

    run_layer(st, g_csqff, tid);     // qff: one sim14 layer

    if (tid < 36) red[tid] = 0.f;
    __syncthreads();

    float xx[NQ], yy[NQ], zz[NQ];
#pragma unroll
    for (int w = 0; w < NQ; ++w) { xx[w] = 0.f; yy[w] = 0.f; zz[w] = 0.f; }

#pragma unroll
    for (int k = 0; k < 16; ++k) {
        int i = tid + 256 * k;
        float2 a = upk(st[sw((uint32_t)i)]);
        float n2 = a.x * a.x + a.y * a.y;
#pragma unroll
        for (int w = 0; w < NQ; ++w) {
            int pbit = 11 - w;
            if (((i >> pbit) & 1) == 0) {
                float2 a1 = upk(st[sw((uint32_t)(i | (1 << pbit)))]);
                xx[w] += 2.f * (a.x * a1.x + a.y * a1.y);
                yy[w] += 2.f * (a.x * a1.y - a.y * a1.x);
                zz[w] += n2;
            } else {
                zz[w] -= n2;
            }
        }
    }
#pragma unroll
    for (int w = 0; w < NQ; ++w) {
        atomicAdd(&red[w], xx[w]);
        atomicAdd(&red[12 + w], yy[w]);
        atomicAdd(&red[24 + w], zz[w]);
    }
    __syncthreads();

    if (tid < ODIM) {
        float acc = b_out[tid];
#pragma unroll
        for (int j = 0; j < 36; ++j) acc += W_out[tid * 36 + j] * red[j];
        out[b * ODIM + tid] = acc;
    }
}

// ---------------------------------------------------------------------------
// Inputs (metadata order): x, W_proj, b_proj, poly_coeffs, mix_re, mix_im,
//                          qff_params, W_out, b_out.  Output: float32 [64,8].
// ---------------------------------------------------------------------------
extern "C" void kernel_launch(void* const* d_in, const int* in_sizes, int n_in,
                              void* d_out, int out_size) {
    (void)in_sizes; (void)n_in; (void)out_size;
    const float* x      = (const float*)d_in[0];
    const float* W_proj = (const float*)d_in[1];
    const float* b_proj = (const float*)d_in[2];
    const float* poly   = (const float*)d_in[3];
    const float* mix_re = (const float*)d_in[4];
    const float* mix_im = (const float*)d_in[5];
    const float* qff    = (const float*)d_in[6];
    const float* W_out  = (const float*)d_in[7];
    const float* b_out  = (const float*)d_in[8];
    float* out = (float*)d_out;

    cudaFuncSetAttribute(circuit_kernel,
                         cudaFuncAttributeMaxDynamicSharedMemorySize, CIRC_SMEM);

    // 5 buffers * 64 * 4096 float2 = 1,310,720 float2 = 163,840 threads * 8
    init_kernel<<<640, 256>>>();
    param_kernel<<<NBLK_CIRC, NROTS>>>(x, W_proj, b_proj, qff);

    float2* w0;
    cudaGetSymbolAddress((void**)&w0, g_work);   // base of g_work
    float2* w1 = w0 + 1 * BATCH * DIM;
    float2* w2 = w0 + 2 * BATCH * DIM;
    float2* w3 = w0 + 3 * BATCH * DIM;
    float2* w4 = w0 + 4 * BATCH * DIM;

    circuit_kernel<<<NBLK_CIRC, 256, CIRC_SMEM>>>((const ull*)w0, w1, mix_re, mix_im);
    circuit_kernel<<<NBLK_CIRC, 256, CIRC_SMEM>>>((const ull*)w1, w2, mix_re, mix_im);
    circuit_kernel<<<NBLK_CIRC, 256, CIRC_SMEM>>>((const ull*)w2, w3, mix_re, mix_im);
    circuit_kernel<<<NBLK_CIRC, 256, CIRC_SMEM>>>((const ull*)w3, w4, mix_re, mix_im);

    final_kernel<<<BATCH, 256>>>(poly, W_out, b_out, out);
}

// round 13
// speedup vs baseline: 1.1388x; 1.0278x over previous
#include <cuda_runtime.h>
#include <cuda_bf16.h>
#include <math.h>
#include <stdint.h>

// ---------------------------------------------------------------------------
// QuantumTSTransformer: 12-qubit statevector sim, packed f32x2 arithmetic.
//   B=64, T=32, DEGREE=4, sim14 2 layers (96 rots), qff layer (48), DIM=4096.
// R12: 3 kernels total.
//   prep: vectorized zero-init + MUFU param projection (merged).
//   circuit_fused: persistent (592 CTAs, 4/SM), ticket queue over all 8192
//     (d,b,t) items; per-(d,b) done counters with red.release / ld.acquire
//     (NO full threadfences — that was R10's mistake). Item body = R7 core:
//     state in 32KB dynamic smem, 8 phases/layer, 4 register qubits
//     (16 packed amps/thread, 256 thr, 64 regs). Final phase fuses mix[t]*psi
//     and flushes via red.global.add.v2.f32.
//   final: assemble, normalize, qff layer, Pauli expvals, output linear.
// ---------------------------------------------------------------------------

#define NQ       12
#define DIM      4096
#define BATCH    64
#define TSTEPS   32
#define NROTS    96
#define QFFROTS  48
#define DEGREE   4
#define FDIM     64
#define ODIM     8
#define NITEMS   (DEGREE * BATCH * TSTEPS)      // 8192
#define NPERS    592                            // 4 CTAs x 148 SMs
#define CIRC_SMEM (DIM * 8 + 1024)              // st + coeffs

typedef unsigned long long ull;

// Scratch (device globals: no allocation allowed)
__device__ float2 g_work[DEGREE + 1][BATCH * DIM];   // work_0=base, work_1..4
__device__ float2 g_cs[BATCH * TSTEPS * NROTS];      // (cos(h), sin(h)) per rot
__device__ float2 g_csqff[QFFROTS];
__device__ unsigned g_ticket;                        // work queue head
__device__ unsigned g_done[DEGREE * BATCH];          // flat: slot = d*64+b

// ---------------- packed f32x2 helpers ----------------
__device__ __forceinline__ ull pk2(float x, float y) {
    ull r; asm("mov.b64 %0, {%1, %2};" : "=l"(r) : "f"(x), "f"(y)); return r;
}
__device__ __forceinline__ ull dup2(float x) { return pk2(x, x); }
__device__ __forceinline__ float2 upk(ull v) {
    float2 r; asm("mov.b64 {%0, %1}, %2;" : "=f"(r.x), "=f"(r.y) : "l"(v)); return r;
}
__device__ __forceinline__ ull swp(ull v) {   // (x,y) -> (y,x)
    ull r;
    asm("{\n\t.reg .b32 lo, hi;\n\tmov.b64 {lo, hi}, %1;\n\tmov.b64 %0, {hi, lo};\n\t}"
        : "=l"(r) : "l"(v));
    return r;
}
__device__ __forceinline__ ull f2mul(ull a, ull b) {
    ull r; asm("mul.rn.f32x2 %0, %1, %2;" : "=l"(r) : "l"(a), "l"(b)); return r;
}
__device__ __forceinline__ ull f2fma(ull a, ull b, ull c) {
    ull r; asm("fma.rn.f32x2 %0, %1, %2, %3;" : "=l"(r) : "l"(a), "l"(b), "l"(c)); return r;
}
__device__ __forceinline__ void red2(float2* p, float2 v) {
    asm volatile("red.global.add.v2.f32 [%0], {%1, %2};"
                 :: "l"(p), "f"(v.x), "f"(v.y) : "memory");
}

// smem slot swizzle: bijective, conflict-free for all phase patterns
__device__ __forceinline__ uint32_t sw(uint32_t i) { return i ^ ((i >> 4) & 0xFu); }

// base address: deposit 8 tid bits into the amplitude-index bits NOT in {P0..P3}
template<int P0, int P1, int P2, int P3>
__device__ __forceinline__ uint32_t phase_base(int tid) {
    constexpr uint32_t M = (1u << P0) | (1u << P1) | (1u << P2) | (1u << P3);
    uint32_t base = 0;
    int tb = 0;
#pragma unroll
    for (int pos = 0; pos < NQ; ++pos) {
        if (!((M >> pos) & 1u)) {
            base |= ((uint32_t)(tid >> tb) & 1u) << pos;
            ++tb;
        }
    }
    return base;
}

template<int P0, int P1, int P2, int P3>
__device__ __forceinline__ uint32_t pidx(uint32_t base, int j) {
    return base
        | ((j & 1) ? (1u << P0) : 0u)
        | ((j & 2) ? (1u << P1) : 0u)
        | ((j & 4) ? (1u << P2) : 0u)
        | ((j & 8) ? (1u << P3) : 0u);
}

// RY on register-bit RB:  a0' = c a0 - s a1 ; a1' = s a0 + c a1  (componentwise)
template<int RB>
__device__ __forceinline__ void gry(ull* r, float2 cs) {
    const ull c2 = dup2(cs.x), s2 = dup2(cs.y), ns2 = dup2(-cs.y);
#pragma unroll
    for (int j = 0; j < 16; ++j) {
        if (!(j & (1 << RB))) {
            ull a0 = r[j], a1 = r[j | (1 << RB)];
            r[j]            = f2fma(c2, a0, f2mul(ns2, a1));
            r[j | (1 << RB)] = f2fma(s2, a0, f2mul(c2, a1));
        }
    }
}

// CRX: control RBC==1, target RBT.  a0' = c a0 - i s a1 ; a1' = c a1 - i s a0.
//  -i s v = (s*v.y, -s*v.x) = mul((s,-s), swap(v))
template<int RBC, int RBT>
__device__ __forceinline__ void gcrx(ull* r, float2 cs) {
    const ull c2 = dup2(cs.x);
    const ull spm = pk2(cs.y, -cs.y);
#pragma unroll
    for (int j = 0; j < 16; ++j) {
        if ((j & (1 << RBC)) && !(j & (1 << RBT))) {
            ull a0 = r[j], a1 = r[j | (1 << RBT)];
            r[j]             = f2fma(c2, a0, f2mul(spm, swp(a1)));
            r[j | (1 << RBT)] = f2fma(c2, a1, f2mul(spm, swp(a0)));
        }
    }
}

#define PHASE_LOAD(P0,P1,P2,P3)                                            \
    uint32_t base = phase_base<P0,P1,P2,P3>(tid);                          \
    ull r[16];                                                             \
    _Pragma("unroll")                                                      \
    for (int j = 0; j < 16; ++j) r[j] = st[sw(pidx<P0,P1,P2,P3>(base, j))];

#define PHASE_STORE(P0,P1,P2,P3)                                           \
    _Pragma("unroll")                                                      \
    for (int j = 0; j < 16; ++j) st[sw(pidx<P0,P1,P2,P3>(base, j))] = r[j];

// ---- the 8 phases of one sim14 layer (wire w <-> amplitude bit 11-w) ----
// Layer = RY ring (idx 0..11) fused with chainA (idx 12..23), then RY ring
// (24..35) fused with chainB (36..47). Groupings preserve gate ordering.

__device__ __forceinline__ void phA1(ull* st, const float2* c, int tid) {
    PHASE_LOAD(11, 0, 1, 2);
    gry<0>(r, c[0]);  gry<1>(r, c[11]); gry<2>(r, c[10]); gry<3>(r, c[9]);
    gcrx<1, 0>(r, c[12]); gcrx<2, 1>(r, c[13]); gcrx<3, 2>(r, c[14]);
    PHASE_STORE(11, 0, 1, 2);
}
__device__ __forceinline__ void phA2(ull* st, const float2* c, int tid) {
    PHASE_LOAD(2, 3, 4, 5);
    gry<1>(r, c[8]); gry<2>(r, c[7]); gry<3>(r, c[6]);
    gcrx<1, 0>(r, c[15]); gcrx<2, 1>(r, c[16]); gcrx<3, 2>(r, c[17]);
    PHASE_STORE(2, 3, 4, 5);
}
__device__ __forceinline__ void phA3(ull* st, const float2* c, int tid) {
    PHASE_LOAD(5, 6, 7, 8);
    gry<1>(r, c[5]); gry<2>(r, c[4]); gry<3>(r, c[3]);
    gcrx<1, 0>(r, c[18]); gcrx<2, 1>(r, c[19]); gcrx<3, 2>(r, c[20]);
    PHASE_STORE(5, 6, 7, 8);
}
__device__ __forceinline__ void phA4(ull* st, const float2* c, int tid) {
    PHASE_LOAD(8, 9, 10, 11);
    gry<1>(r, c[2]); gry<2>(r, c[1]);
    gcrx<1, 0>(r, c[21]); gcrx<2, 1>(r, c[22]); gcrx<3, 2>(r, c[23]);
    PHASE_STORE(8, 9, 10, 11);
}
__device__ __forceinline__ void phB1(ull* st, const float2* c, int tid) {
    PHASE_LOAD(1, 0, 11, 10);
    gry<0>(r, c[34]); gry<1>(r, c[35]); gry<2>(r, c[24]); gry<3>(r, c[25]);
    gcrx<1, 0>(r, c[36]); gcrx<2, 1>(r, c[37]); gcrx<3, 2>(r, c[38]);
    PHASE_STORE(1, 0, 11, 10);
}
__device__ __forceinline__ void phB2(ull* st, const float2* c, int tid) {
    PHASE_LOAD(10, 9, 8, 7);
    gry<1>(r, c[26]); gry<2>(r, c[27]); gry<3>(r, c[28]);
    gcrx<1, 0>(r, c[39]); gcrx<2, 1>(r, c[40]); gcrx<3, 2>(r, c[41]);
    PHASE_STORE(10, 9, 8, 7);
}
__device__ __forceinline__ void phB3(ull* st, const float2* c, int tid) {
    PHASE_LOAD(7, 6, 5, 4);
    gry<1>(r, c[29]); gry<2>(r, c[30]); gry<3>(r, c[31]);
    gcrx<1, 0>(r, c[42]); gcrx<2, 1>(r, c[43]); gcrx<3, 2>(r, c[44]);
    PHASE_STORE(7, 6, 5, 4);
}
__device__ __forceinline__ void phB4(ull* st, const float2* c, int tid) {
    PHASE_LOAD(4, 3, 2, 1);
    gry<1>(r, c[32]); gry<2>(r, c[33]);
    gcrx<1, 0>(r, c[45]); gcrx<2, 1>(r, c[46]); gcrx<3, 2>(r, c[47]);
    PHASE_STORE(4, 3, 2, 1);
}

__device__ __forceinline__ void run_layer(ull* st, const float2* c, int tid) {
    phA1(st, c, tid); __syncthreads();
    phA2(st, c, tid); __syncthreads();
    phA3(st, c, tid); __syncthreads();
    phA4(st, c, tid); __syncthreads();
    phB1(st, c, tid); __syncthreads();
    phB2(st, c, tid); __syncthreads();
    phB3(st, c, tid); __syncthreads();
    phB4(st, c, tid); __syncthreads();
}

// ---------------------------------------------------------------------------
// Kernel 1: merged prep.
//   blocks [0, 640):    vectorized zero/init of g_work (+ queue reset in blk 0)
//   blocks [640, 2688): param projection for bt = blockIdx.x - 640
// ---------------------------------------------------------------------------
#define INIT_BLKS 640
__global__ void prep_kernel(const float* __restrict__ x,
                            const float* __restrict__ Wp,
                            const float* __restrict__ bp,
                            const float* __restrict__ qff) {
    if (blockIdx.x < INIT_BLKS) {
        if (blockIdx.x == 0) {                 // reset queue + done counters
            if (threadIdx.x == 0) g_ticket = 0u;
            if (threadIdx.x < DEGREE * BATCH) g_done[threadIdx.x] = 0u;
        }
        uint32_t tgid = blockIdx.x * 256 + threadIdx.x;   // 0..163839
        uint32_t c0 = tgid * 8;                            // first float2 index
        float4* p = (float4*)&g_work[0][0];
        float4 z = make_float4(0.f, 0.f, 0.f, 0.f);
        bool one = (c0 < (uint32_t)(BATCH * DIM)) && ((c0 & (DIM - 1)) == 0);
        float4 z0 = z;
        if (one) z0.x = 1.f;
        p[tgid * 4 + 0] = z0;
        p[tgid * 4 + 1] = z;
        p[tgid * 4 + 2] = z;
        p[tgid * 4 + 3] = z;
        return;
    }
    __shared__ float4 xr[FDIM / 4];            // 16 float4
    int bt = blockIdx.x - INIT_BLKS;           // 0..2047
    int r = threadIdx.x;                       // 0..255, only 0..95 produce
    if (r < FDIM / 4) xr[r] = ((const float4*)(x + bt * FDIM))[r];
    __syncthreads();
    if (r < NROTS) {
        const float4* wrow = (const float4*)(Wp + r * FDIM);
        float acc = bp[r];
#pragma unroll
        for (int f = 0; f < FDIM / 4; ++f) {
            float4 xv = xr[f], wv = wrow[f];
            acc += xv.x * wv.x + xv.y * wv.y + xv.z * wv.z + xv.w * wv.w;
        }
        float sg = 1.0f / (1.0f + __expf(-acc));
        float h = 3.14159265358979323846f * sg;    // theta/2 = pi * sigmoid
        float sv, cv; __sincosf(h, &sv, &cv);
        g_cs[bt * NROTS + r] = make_float2(cv, sv);
        if (bt == 0 && r < QFFROTS) {
            float hq = 0.5f * qff[r];
            float sq, cq; __sincosf(hq, &sq, &cq);
            g_csqff[r] = make_float2(cq, sq);
        }
    }
}

// ---------------------------------------------------------------------------
// Kernel 2: persistent fused circuits. 592 CTAs pull (d,b,t) items off a
// ticket queue. Completion signaled with red.release; waits use ld.acquire.
// slot = item >> 5 = d*64+b; dependency slot = slot - 64 (d>0 only).
// ---------------------------------------------------------------------------
__global__ void __launch_bounds__(256, 4)
circuit_fused(const float* __restrict__ mix_re, const float* __restrict__ mix_im) {
    extern __shared__ ull dsm[];
    ull* st = dsm;                            // DIM
    float2* cc = (float2*)(dsm + DIM);        // 96 coeffs + mix at [96]
    __shared__ unsigned s_ticket;

    const int tid = threadIdx.x;
    unsigned prev_slot = 0xFFFFFFFFu;         // no completed item yet

    for (;;) {
        __syncthreads();                      // all threads done with prev item
        if (tid == 0) {
            // signal prev item (bar.sync gave CTA-scope visibility of all
            // threads' REDs; release publishes them at GPU scope)
            if (prev_slot != 0xFFFFFFFFu)
                asm volatile("red.release.gpu.global.add.u32 [%0], 1;"
                             :: "l"(&g_done[prev_slot]) : "memory");
            s_ticket = atomicAdd(&g_ticket, 1u);
        }
        __syncthreads();
        const unsigned item = s_ticket;
        if (item >= NITEMS) break;
        const unsigned slot = item >> 5;      // d*64 + b
        const int b = slot & 63;
        const int t = item & 31;
        const int d = slot >> 6;

        if (slot >= 64 && tid == 0) {         // d > 0: wait for 32 producers
            unsigned v;
            for (;;) {
                asm volatile("ld.acquire.gpu.global.u32 %0, [%1];"
                             : "=r"(v) : "l"(&g_done[slot - 64]) : "memory");
                if (v >= (unsigned)TSTEPS) break;
                __nanosleep(64);
            }
        }
        __syncthreads();                      // broadcast acquire to CTA

        const ull* win = (const ull*)&g_work[d][b * DIM];
        float2* wout = &g_work[d + 1][b * DIM];

        // stage input state + coefficients
#pragma unroll
        for (int k = 0; k < 16; ++k) {
            int i = tid + 256 * k;
            st[sw((uint32_t)i)] = win[i];
        }
        if (tid < NROTS) cc[tid] = g_cs[(b * TSTEPS + t) * NROTS + tid];
        if (tid == NROTS) cc[NROTS] = make_float2(mix_re[t], mix_im[t]);
        __syncthreads();

        run_layer(st, cc, tid);               // layer 0 (8 phases)
        const float2* c1 = cc + 48;
        phA1(st, c1, tid); __syncthreads();
        phA2(st, c1, tid); __syncthreads();
        phA3(st, c1, tid); __syncthreads();
        phA4(st, c1, tid); __syncthreads();
        phB1(st, c1, tid); __syncthreads();
        phB2(st, c1, tid); __syncthreads();
        phB3(st, c1, tid); __syncthreads();
        {   // phB4 without store: mix[t] * psi -> red.global directly
            PHASE_LOAD(4, 3, 2, 1);
            gry<1>(r, c1[32]); gry<2>(r, c1[33]);
            gcrx<1, 0>(r, c1[45]); gcrx<2, 1>(r, c1[46]); gcrx<3, 2>(r, c1[47]);
            float2 mx = cc[NROTS];
            const ull mr2 = dup2(mx.x);
            const ull mpm = pk2(-mx.y, mx.y);
#pragma unroll
            for (int j = 0; j < 16; ++j) {
                uint32_t i = pidx<4, 3, 2, 1>(base, j);
                ull v = f2fma(mr2, r[j], f2mul(mpm, swp(r[j])));
                red2(&wout[i], upk(v));
            }
        }
        prev_slot = slot;                     // signal at next loop top
    }
}

// ---------------------------------------------------------------------------
// Kernel 3: assemble acc, normalize, qff layer, Pauli expvals, output linear.
// grid = 64 (one CTA per batch), 256 threads.
// ---------------------------------------------------------------------------
__global__ void final_kernel(const float* __restrict__ poly,
                             const float* __restrict__ W_out,
                             const float* __restrict__ b_out,
                             float* __restrict__ out) {
    __shared__ ull st[DIM];
    __shared__ float red[37];            // [0..35] expvals, [36] sumsq
    const int tid = threadIdx.x;
    const int b = blockIdx.x;

    float p[DEGREE + 1];
#pragma unroll
    for (int d = 0; d <= DEGREE; ++d) p[d] = poly[d];
    float sabs = 0.f;
#pragma unroll
    for (int d = 0; d <= DEGREE; ++d) sabs += fabsf(p[d]);
    const float inv_s = 1.f / sabs;

    if (tid == 0) red[36] = 0.f;
    const ull* wflat = (const ull*)&g_work[0][0];
    float lsq = 0.f;
#pragma unroll
    for (int k = 0; k < 16; ++k) {
        int i = tid + 256 * k;
        ull v = 0ull;
#pragma unroll
        for (int d = 0; d <= DEGREE; ++d) {
            ull w = wflat[(size_t)d * (BATCH * DIM) + b * DIM + i];
            v = f2fma(dup2(p[d]), w, v);
        }
        v = f2mul(dup2(inv_s), v);
        st[sw((uint32_t)i)] = v;
        float2 vf = upk(v);
        lsq += vf.x * vf.x + vf.y * vf.y;
    }
#pragma unroll
    for (int o = 16; o > 0; o >>= 1) lsq += __shfl_xor_sync(0xffffffffu, lsq, o);
    if ((tid & 31) == 0) atomicAdd(&red[36], lsq);
    __syncthreads();

    const float f = 1.f / (sqrtf(red[36]) + 1e-9f);
    const ull f2 = dup2(f);
#pragma unroll
    for (int k = 0; k < 16; ++k) {
        int i = tid + 256 * k;
        uint32_t s_ = sw((uint32_t)i);
        st[s_] = f2mul(f2, st[s_]);
    }
    __syncthreads();

    run_layer(st, g_csqff, tid);     // qff: one sim14 layer

    if (tid < 36) red[tid] = 0.f;
    __syncthreads();

    float xx[NQ], yy[NQ], zz[NQ];
#pragma unroll
    for (int w = 0; w < NQ; ++w) { xx[w] = 0.f; yy[w] = 0.f; zz[w] = 0.f; }

#pragma unroll
    for (int k = 0; k < 16; ++k) {
        int i = tid + 256 * k;
        float2 a = upk(st[sw((uint32_t)i)]);
        float n2 = a.x * a.x + a.y * a.y;
#pragma unroll
        for (int w = 0; w < NQ; ++w) {
            int pbit = 11 - w;
            if (((i >> pbit) & 1) == 0) {
                float2 a1 = upk(st[sw((uint32_t)(i | (1 << pbit)))]);
                xx[w] += 2.f * (a.x * a1.x + a.y * a1.y);
                yy[w] += 2.f * (a.x * a1.y - a.y * a1.x);
                zz[w] += n2;
            } else {
                zz[w] -= n2;
            }
        }
    }
#pragma unroll
    for (int w = 0; w < NQ; ++w) {
        atomicAdd(&red[w], xx[w]);
        atomicAdd(&red[12 + w], yy[w]);
        atomicAdd(&red[24 + w], zz[w]);
    }
    __syncthreads();

    if (tid < ODIM) {
        float acc = b_out[tid];
#pragma unroll
        for (int j = 0; j < 36; ++j) acc += W_out[tid * 36 + j] * red[j];
        out[b * ODIM + tid] = acc;
    }
}

// ---------------------------------------------------------------------------
// Inputs (metadata order): x, W_proj, b_proj, poly_coeffs, mix_re, mix_im,
//                          qff_params, W_out, b_out.  Output: float32 [64,8].
// ---------------------------------------------------------------------------
extern "C" void kernel_launch(void* const* d_in, const int* in_sizes, int n_in,
                              void* d_out, int out_size) {
    (void)in_sizes; (void)n_in; (void)out_size;
    const float* x      = (const float*)d_in[0];
    const float* W_proj = (const float*)d_in[1];
    const float* b_proj = (const float*)d_in[2];
    const float* poly   = (const float*)d_in[3];
    const float* mix_re = (const float*)d_in[4];
    const float* mix_im = (const float*)d_in[5];
    const float* qff    = (const float*)d_in[6];
    const float* W_out  = (const float*)d_in[7];
    const float* b_out  = (const float*)d_in[8];
    float* out = (float*)d_out;

    cudaFuncSetAttribute(circuit_fused,
                         cudaFuncAttributeMaxDynamicSharedMemorySize, CIRC_SMEM);

    prep_kernel<<<INIT_BLKS + BATCH * TSTEPS, 256>>>(x, W_proj, b_proj, qff);
    circuit_fused<<<NPERS, 256, CIRC_SMEM>>>(mix_re, mix_im);
    final_kernel<<<BATCH, 256>>>(poly, W_out, b_out, out);
}

// round 14
// speedup vs baseline: 1.1817x; 1.0377x over previous
#include <cuda_runtime.h>
#include <cuda_bf16.h>
#include <math.h>
#include <stdint.h>

// ---------------------------------------------------------------------------
// QuantumTSTransformer: 12-qubit statevector sim, packed f32x2 arithmetic.
//   B=64, T=32, DEGREE=4, sim14 2 layers (96 rots), qff layer (48), DIM=4096.
// R13: 3 kernels.
//   prep: zero g_work[1..4] + queue reset (512 blocks). g_work[0] is never
//     materialized — the |0..0> state is analytic.
//   circuit_fused: persistent (592 CTAs, 4/SM), ticket queue over 8192
//     (d,b,t) items, red.release / ld.acquire done-counters. d=0 items
//     compute their own rotation params (projection + MUFU) into smem+g_cs
//     and start from |0..0> directly in registers (no staging phase).
//   final: analytic p[0] term, assemble, normalize, qff (params computed
//     in-kernel), Pauli expvals, output linear.
// ---------------------------------------------------------------------------

#define NQ       12
#define DIM      4096
#define BATCH    64
#define TSTEPS   32
#define NROTS    96
#define QFFROTS  48
#define DEGREE   4
#define FDIM     64
#define ODIM     8
#define NITEMS   (DEGREE * BATCH * TSTEPS)      // 8192
#define NPERS    592                            // 4 CTAs x 148 SMs
#define CIRC_SMEM (DIM * 8 + 1024)              // st + coeffs

typedef unsigned long long ull;

// Scratch (device globals: no allocation allowed)
__device__ float2 g_work[DEGREE + 1][BATCH * DIM];   // [0] unused (analytic)
__device__ float2 g_cs[BATCH * TSTEPS * NROTS];      // (cos(h), sin(h)) per rot
__device__ unsigned g_ticket;                        // work queue head
__device__ unsigned g_done[DEGREE * BATCH];          // flat: slot = d*64+b

// ---------------- packed f32x2 helpers ----------------
__device__ __forceinline__ ull pk2(float x, float y) {
    ull r; asm("mov.b64 %0, {%1, %2};" : "=l"(r) : "f"(x), "f"(y)); return r;
}
__device__ __forceinline__ ull dup2(float x) { return pk2(x, x); }
__device__ __forceinline__ float2 upk(ull v) {
    float2 r; asm("mov.b64 {%0, %1}, %2;" : "=f"(r.x), "=f"(r.y) : "l"(v)); return r;
}
__device__ __forceinline__ ull swp(ull v) {   // (x,y) -> (y,x)
    ull r;
    asm("{\n\t.reg .b32 lo, hi;\n\tmov.b64 {lo, hi}, %1;\n\tmov.b64 %0, {hi, lo};\n\t}"
        : "=l"(r) : "l"(v));
    return r;
}
__device__ __forceinline__ ull f2mul(ull a, ull b) {
    ull r; asm("mul.rn.f32x2 %0, %1, %2;" : "=l"(r) : "l"(a), "l"(b)); return r;
}
__device__ __forceinline__ ull f2fma(ull a, ull b, ull c) {
    ull r; asm("fma.rn.f32x2 %0, %1, %2, %3;" : "=l"(r) : "l"(a), "l"(b), "l"(c)); return r;
}
__device__ __forceinline__ void red2(float2* p, float2 v) {
    asm volatile("red.global.add.v2.f32 [%0], {%1, %2};"
                 :: "l"(p), "f"(v.x), "f"(v.y) : "memory");
}

// smem slot swizzle: bijective, conflict-free for all phase patterns
__device__ __forceinline__ uint32_t sw(uint32_t i) { return i ^ ((i >> 4) & 0xFu); }

// base address: deposit 8 tid bits into the amplitude-index bits NOT in {P0..P3}
template<int P0, int P1, int P2, int P3>
__device__ __forceinline__ uint32_t phase_base(int tid) {
    constexpr uint32_t M = (1u << P0) | (1u << P1) | (1u << P2) | (1u << P3);
    uint32_t base = 0;
    int tb = 0;
#pragma unroll
    for (int pos = 0; pos < NQ; ++pos) {
        if (!((M >> pos) & 1u)) {
            base |= ((uint32_t)(tid >> tb) & 1u) << pos;
            ++tb;
        }
    }
    return base;
}

template<int P0, int P1, int P2, int P3>
__device__ __forceinline__ uint32_t pidx(uint32_t base, int j) {
    return base
        | ((j & 1) ? (1u << P0) : 0u)
        | ((j & 2) ? (1u << P1) : 0u)
        | ((j & 4) ? (1u << P2) : 0u)
        | ((j & 8) ? (1u << P3) : 0u);
}

// RY on register-bit RB:  a0' = c a0 - s a1 ; a1' = s a0 + c a1  (componentwise)
template<int RB>
__device__ __forceinline__ void gry(ull* r, float2 cs) {
    const ull c2 = dup2(cs.x), s2 = dup2(cs.y), ns2 = dup2(-cs.y);
#pragma unroll
    for (int j = 0; j < 16; ++j) {
        if (!(j & (1 << RB))) {
            ull a0 = r[j], a1 = r[j | (1 << RB)];
            r[j]            = f2fma(c2, a0, f2mul(ns2, a1));
            r[j | (1 << RB)] = f2fma(s2, a0, f2mul(c2, a1));
        }
    }
}

// CRX: control RBC==1, target RBT.  a0' = c a0 - i s a1 ; a1' = c a1 - i s a0.
//  -i s v = (s*v.y, -s*v.x) = mul((s,-s), swap(v))
template<int RBC, int RBT>
__device__ __forceinline__ void gcrx(ull* r, float2 cs) {
    const ull c2 = dup2(cs.x);
    const ull spm = pk2(cs.y, -cs.y);
#pragma unroll
    for (int j = 0; j < 16; ++j) {
        if ((j & (1 << RBC)) && !(j & (1 << RBT))) {
            ull a0 = r[j], a1 = r[j | (1 << RBT)];
            r[j]             = f2fma(c2, a0, f2mul(spm, swp(a1)));
            r[j | (1 << RBT)] = f2fma(c2, a1, f2mul(spm, swp(a0)));
        }
    }
}

#define PHASE_LOAD(P0,P1,P2,P3)                                            \
    uint32_t base = phase_base<P0,P1,P2,P3>(tid);                          \
    ull r[16];                                                             \
    _Pragma("unroll")                                                      \
    for (int j = 0; j < 16; ++j) r[j] = st[sw(pidx<P0,P1,P2,P3>(base, j))];

#define PHASE_STORE(P0,P1,P2,P3)                                           \
    _Pragma("unroll")                                                      \
    for (int j = 0; j < 16; ++j) st[sw(pidx<P0,P1,P2,P3>(base, j))] = r[j];

// ---- the 8 phases of one sim14 layer (wire w <-> amplitude bit 11-w) ----
// Layer = RY ring (idx 0..11) fused with chainA (idx 12..23), then RY ring
// (24..35) fused with chainB (36..47). Groupings preserve gate ordering.

__device__ __forceinline__ void phA1_body(ull* r, const float2* c) {
    gry<0>(r, c[0]);  gry<1>(r, c[11]); gry<2>(r, c[10]); gry<3>(r, c[9]);
    gcrx<1, 0>(r, c[12]); gcrx<2, 1>(r, c[13]); gcrx<3, 2>(r, c[14]);
}
__device__ __forceinline__ void phA1(ull* st, const float2* c, int tid) {
    PHASE_LOAD(11, 0, 1, 2);
    phA1_body(r, c);
    PHASE_STORE(11, 0, 1, 2);
}
// phA1 starting from the analytic |0..0> state (d=0 items): no load phase.
__device__ __forceinline__ void phA1_zero(ull* st, const float2* c, int tid) {
    uint32_t base = phase_base<11, 0, 1, 2>(tid);
    ull r[16];
#pragma unroll
    for (int j = 0; j < 16; ++j) r[j] = 0ull;
    if (tid == 0) r[0] = pk2(1.f, 0.f);
    phA1_body(r, c);
    PHASE_STORE(11, 0, 1, 2);
}
__device__ __forceinline__ void phA2(ull* st, const float2* c, int tid) {
    PHASE_LOAD(2, 3, 4, 5);
    gry<1>(r, c[8]); gry<2>(r, c[7]); gry<3>(r, c[6]);
    gcrx<1, 0>(r, c[15]); gcrx<2, 1>(r, c[16]); gcrx<3, 2>(r, c[17]);
    PHASE_STORE(2, 3, 4, 5);
}
__device__ __forceinline__ void phA3(ull* st, const float2* c, int tid) {
    PHASE_LOAD(5, 6, 7, 8);
    gry<1>(r, c[5]); gry<2>(r, c[4]); gry<3>(r, c[3]);
    gcrx<1, 0>(r, c[18]); gcrx<2, 1>(r, c[19]); gcrx<3, 2>(r, c[20]);
    PHASE_STORE(5, 6, 7, 8);
}
__device__ __forceinline__ void phA4(ull* st, const float2* c, int tid) {
    PHASE_LOAD(8, 9, 10, 11);
    gry<1>(r, c[2]); gry<2>(r, c[1]);
    gcrx<1, 0>(r, c[21]); gcrx<2, 1>(r, c[22]); gcrx<3, 2>(r, c[23]);
    PHASE_STORE(8, 9, 10, 11);
}
__device__ __forceinline__ void phB1(ull* st, const float2* c, int tid) {
    PHASE_LOAD(1, 0, 11, 10);
    gry<0>(r, c[34]); gry<1>(r, c[35]); gry<2>(r, c[24]); gry<3>(r, c[25]);
    gcrx<1, 0>(r, c[36]); gcrx<2, 1>(r, c[37]); gcrx<3, 2>(r, c[38]);
    PHASE_STORE(1, 0, 11, 10);
}
__device__ __forceinline__ void phB2(ull* st, const float2* c, int tid) {
    PHASE_LOAD(10, 9, 8, 7);
    gry<1>(r, c[26]); gry<2>(r, c[27]); gry<3>(r, c[28]);
    gcrx<1, 0>(r, c[39]); gcrx<2, 1>(r, c[40]); gcrx<3, 2>(r, c[41]);
    PHASE_STORE(10, 9, 8, 7);
}
__device__ __forceinline__ void phB3(ull* st, const float2* c, int tid) {
    PHASE_LOAD(7, 6, 5, 4);
    gry<1>(r, c[29]); gry<2>(r, c[30]); gry<3>(r, c[31]);
    gcrx<1, 0>(r, c[42]); gcrx<2, 1>(r, c[43]); gcrx<3, 2>(r, c[44]);
    PHASE_STORE(7, 6, 5, 4);
}
__device__ __forceinline__ void phB4(ull* st, const float2* c, int tid) {
    PHASE_LOAD(4, 3, 2, 1);
    gry<1>(r, c[32]); gry<2>(r, c[33]);
    gcrx<1, 0>(r, c[45]); gcrx<2, 1>(r, c[46]); gcrx<3, 2>(r, c[47]);
    PHASE_STORE(4, 3, 2, 1);
}

__device__ __forceinline__ void run_layer(ull* st, const float2* c, int tid) {
    phA1(st, c, tid); __syncthreads();
    phA2(st, c, tid); __syncthreads();
    phA3(st, c, tid); __syncthreads();
    phA4(st, c, tid); __syncthreads();
    phB1(st, c, tid); __syncthreads();
    phB2(st, c, tid); __syncthreads();
    phB3(st, c, tid); __syncthreads();
    phB4(st, c, tid); __syncthreads();
}

// ---------------------------------------------------------------------------
// Kernel 1: prep = zero g_work[1..4] (+ queue reset in block 0).
// 512 blocks x 256 threads, 4 x float4 per thread (8.4 MB).
// ---------------------------------------------------------------------------
#define INIT_BLKS 512
__global__ void prep_kernel() {
    if (blockIdx.x == 0) {
        if (threadIdx.x == 0) g_ticket = 0u;
        if (threadIdx.x < DEGREE * BATCH) g_done[threadIdx.x] = 0u;
    }
    uint32_t tgid = blockIdx.x * 256 + threadIdx.x;     // 0..131071
    // buffer 1 starts at float4 index 131072 (= BATCH*DIM float2 / 2)
    float4* p = (float4*)&g_work[0][0] + 131072 + (size_t)tgid * 4;
    float4 z = make_float4(0.f, 0.f, 0.f, 0.f);
    p[0] = z; p[1] = z; p[2] = z; p[3] = z;
}

// ---------------------------------------------------------------------------
// Kernel 2: persistent fused circuits. 592 CTAs pull (d,b,t) items off a
// ticket queue. d=0 items compute their own params and start from |0..0>.
// Completion: red.release; waits: ld.acquire. slot = d*64+b; dep = slot-64.
// ---------------------------------------------------------------------------
__global__ void __launch_bounds__(256, 4)
circuit_fused(const float* __restrict__ x,
              const float* __restrict__ Wp,
              const float* __restrict__ bp,
              const float* __restrict__ mix_re,
              const float* __restrict__ mix_im) {
    extern __shared__ ull dsm[];
    ull* st = dsm;                            // DIM
    float2* cc = (float2*)(dsm + DIM);        // 96 coeffs + mix at [96]
    __shared__ unsigned s_ticket;

    const int tid = threadIdx.x;
    unsigned prev_slot = 0xFFFFFFFFu;         // no completed item yet

    for (;;) {
        __syncthreads();                      // all threads done with prev item
        if (tid == 0) {
            if (prev_slot != 0xFFFFFFFFu)
                asm volatile("red.release.gpu.global.add.u32 [%0], 1;"
                             :: "l"(&g_done[prev_slot]) : "memory");
            s_ticket = atomicAdd(&g_ticket, 1u);
        }
        __syncthreads();
        const unsigned item = s_ticket;
        if (item >= NITEMS) break;
        const unsigned slot = item >> 5;      // d*64 + b
        const int b = slot & 63;
        const int t = item & 31;
        const int d = slot >> 6;
        const int bt = b * TSTEPS + t;

        if (d == 0) {
            // ---- compute this (b,t)'s rotation params in-item ----
            float4* xr = (float4*)st;         // reuse st head as x staging
            if (tid < FDIM / 4) xr[tid] = ((const float4*)(x + bt * FDIM))[tid];
            __syncthreads();
            if (tid < NROTS) {
                const float4* wrow = (const float4*)(Wp + tid * FDIM);
                float acc = bp[tid];
#pragma unroll
                for (int f = 0; f < FDIM / 4; ++f) {
                    float4 xv = xr[f], wv = wrow[f];
                    acc += xv.x * wv.x + xv.y * wv.y + xv.z * wv.z + xv.w * wv.w;
                }
                float sg = 1.0f / (1.0f + __expf(-acc));
                float h = 3.14159265358979323846f * sg;
                float sv, cv; __sincosf(h, &sv, &cv);
                float2 cs_ = make_float2(cv, sv);
                cc[tid] = cs_;
                g_cs[bt * NROTS + tid] = cs_;   // publish for d>0 consumers
            }
            if (tid == NROTS) cc[NROTS] = make_float2(mix_re[t], mix_im[t]);
            __syncthreads();
            phA1_zero(st, cc, tid); __syncthreads();   // analytic |0..0> start
        } else {
            // ---- wait for the 32 producers of work[d] for this b ----
            if (tid == 0) {
                unsigned v;
                for (;;) {
                    asm volatile("ld.acquire.gpu.global.u32 %0, [%1];"
                                 : "=r"(v) : "l"(&g_done[slot - 64]) : "memory");
                    if (v >= (unsigned)TSTEPS) break;
                    __nanosleep(64);
                }
            }
            __syncthreads();                  // broadcast acquire to CTA

            const ull* win = (const ull*)&g_work[d][b * DIM];
#pragma unroll
            for (int k = 0; k < 16; ++k) {
                int i = tid + 256 * k;
                st[sw((uint32_t)i)] = win[i];
            }
            if (tid < NROTS) cc[tid] = g_cs[bt * NROTS + tid];
            if (tid == NROTS) cc[NROTS] = make_float2(mix_re[t], mix_im[t]);
            __syncthreads();
            phA1(st, cc, tid); __syncthreads();
        }

        // remaining 7 phases of layer 0
        phA2(st, cc, tid); __syncthreads();
        phA3(st, cc, tid); __syncthreads();
        phA4(st, cc, tid); __syncthreads();
        phB1(st, cc, tid); __syncthreads();
        phB2(st, cc, tid); __syncthreads();
        phB3(st, cc, tid); __syncthreads();
        phB4(st, cc, tid); __syncthreads();
        // layer 1: first 7 phases, last phase fused with mix+flush
        const float2* c1 = cc + 48;
        phA1(st, c1, tid); __syncthreads();
        phA2(st, c1, tid); __syncthreads();
        phA3(st, c1, tid); __syncthreads();
        phA4(st, c1, tid); __syncthreads();
        phB1(st, c1, tid); __syncthreads();
        phB2(st, c1, tid); __syncthreads();
        phB3(st, c1, tid); __syncthreads();
        {   // phB4 without store: mix[t] * psi -> red.global directly
            float2* wout = &g_work[d + 1][b * DIM];
            PHASE_LOAD(4, 3, 2, 1);
            gry<1>(r, c1[32]); gry<2>(r, c1[33]);
            gcrx<1, 0>(r, c1[45]); gcrx<2, 1>(r, c1[46]); gcrx<3, 2>(r, c1[47]);
            float2 mx = cc[NROTS];
            const ull mr2 = dup2(mx.x);
            const ull mpm = pk2(-mx.y, mx.y);
#pragma unroll
            for (int j = 0; j < 16; ++j) {
                uint32_t i = pidx<4, 3, 2, 1>(base, j);
                ull v = f2fma(mr2, r[j], f2mul(mpm, swp(r[j])));
                red2(&wout[i], upk(v));
            }
        }
        prev_slot = slot;                     // signal at next loop top
    }
}

// ---------------------------------------------------------------------------
// Kernel 3: analytic p[0] + assemble, normalize, qff layer (params computed
// here), Pauli expvals, output linear. grid = 64, 256 threads.
// ---------------------------------------------------------------------------
__global__ void final_kernel(const float* __restrict__ poly,
                             const float* __restrict__ qff,
                             const float* __restrict__ W_out,
                             const float* __restrict__ b_out,
                             float* __restrict__ out) {
    __shared__ ull st[DIM];
    __shared__ float red[37];            // [0..35] expvals, [36] sumsq
    __shared__ float2 csqff[QFFROTS];
    const int tid = threadIdx.x;
    const int b = blockIdx.x;

    if (tid < QFFROTS) {
        float hq = 0.5f * qff[tid];
        float sq, cq; __sincosf(hq, &sq, &cq);
        csqff[tid] = make_float2(cq, sq);
    }

    float p[DEGREE + 1];
#pragma unroll
    for (int d = 0; d <= DEGREE; ++d) p[d] = poly[d];
    float sabs = 0.f;
#pragma unroll
    for (int d = 0; d <= DEGREE; ++d) sabs += fabsf(p[d]);
    const float inv_s = 1.f / sabs;

    if (tid == 0) red[36] = 0.f;
    const ull* wflat = (const ull*)&g_work[0][0];
    float lsq = 0.f;
#pragma unroll
    for (int k = 0; k < 16; ++k) {
        int i = tid + 256 * k;
        ull v = 0ull;
#pragma unroll
        for (int d = 1; d <= DEGREE; ++d) {
            ull w = wflat[(size_t)d * (BATCH * DIM) + b * DIM + i];
            v = f2fma(dup2(p[d]), w, v);
        }
        if (i == 0) v = f2fma(dup2(p[0]), pk2(1.f, 0.f), v);  // analytic base
        v = f2mul(dup2(inv_s), v);
        st[sw((uint32_t)i)] = v;
        float2 vf = upk(v);
        lsq += vf.x * vf.x + vf.y * vf.y;
    }
#pragma unroll
    for (int o = 16; o > 0; o >>= 1) lsq += __shfl_xor_sync(0xffffffffu, lsq, o);
    if ((tid & 31) == 0) atomicAdd(&red[36], lsq);
    __syncthreads();

    const float f = 1.f / (sqrtf(red[36]) + 1e-9f);
    const ull f2 = dup2(f);
#pragma unroll
    for (int k = 0; k < 16; ++k) {
        int i = tid + 256 * k;
        uint32_t s_ = sw((uint32_t)i);
        st[s_] = f2mul(f2, st[s_]);
    }
    __syncthreads();

    run_layer(st, csqff, tid);       // qff: one sim14 layer

    if (tid < 36) red[tid] = 0.f;
    __syncthreads();

    float xx[NQ], yy[NQ], zz[NQ];
#pragma unroll
    for (int w = 0; w < NQ; ++w) { xx[w] = 0.f; yy[w] = 0.f; zz[w] = 0.f; }

#pragma unroll
    for (int k = 0; k < 16; ++k) {
        int i = tid + 256 * k;
        float2 a = upk(st[sw((uint32_t)i)]);
        float n2 = a.x * a.x + a.y * a.y;
#pragma unroll
        for (int w = 0; w < NQ; ++w) {
            int pbit = 11 - w;
            if (((i >> pbit) & 1) == 0) {
                float2 a1 = upk(st[sw((uint32_t)(i | (1 << pbit)))]);
                xx[w] += 2.f * (a.x * a1.x + a.y * a1.y);
                yy[w] += 2.f * (a.x * a1.y - a.y * a1.x);
                zz[w] += n2;
            } else {
                zz[w] -= n2;
            }
        }
    }
#pragma unroll
    for (int w = 0; w < NQ; ++w) {
        atomicAdd(&red[w], xx[w]);
        atomicAdd(&red[12 + w], yy[w]);
        atomicAdd(&red[24 + w], zz[w]);
    }
    __syncthreads();

    if (tid < ODIM) {
        float acc = b_out[tid];
#pragma unroll
        for (int j = 0; j < 36; ++j) acc += W_out[tid * 36 + j] * red[j];
        out[b * ODIM + tid] = acc;
    }
}

// ---------------------------------------------------------------------------
// Inputs (metadata order): x, W_proj, b_proj, poly_coeffs, mix_re, mix_im,
//                          qff_params, W_out, b_out.  Output: float32 [64,8].
// ---------------------------------------------------------------------------
extern "C" void kernel_launch(void* const* d_in, const int* in_sizes, int n_in,
                              void* d_out, int out_size) {
    (void)in_sizes; (void)n_in; (void)out_size;
    const float* x      = (const float*)d_in[0];
    const float* W_proj = (const float*)d_in[1];
    const float* b_proj = (const float*)d_in[2];
    const float* poly   = (const float*)d_in[3];
    const float* mix_re = (const float*)d_in[4];
    const float* mix_im = (const float*)d_in[5];
    const float* qff    = (const float*)d_in[6];
    const float* W_out  = (const float*)d_in[7];
    const float* b_out  = (const float*)d_in[8];
    float* out = (float*)d_out;

    cudaFuncSetAttribute(circuit_fused,
                         cudaFuncAttributeMaxDynamicSharedMemorySize, CIRC_SMEM);

    prep_kernel<<<INIT_BLKS, 256>>>();
    circuit_fused<<<NPERS, 256, CIRC_SMEM>>>(x, W_proj, b_proj, mix_re, mix_im);
    final_kernel<<<BATCH, 256>>>(poly, qff, W_out, b_out, out);
}